// round 2
// baseline (speedup 1.0000x reference)
#include <cuda_runtime.h>
#include <math.h>

#define NEGV -65504.0f

// ---------------- scratch (device globals; no allocations allowed) ----------
__device__ float g_scores[64 * 512 * 128];   // reused: [64,512,128] then [64,128,512]
__device__ float g_x[64 * 512 * 640];        // attention outputs (x1 then x2)
__device__ float g_att[64 * 512];            // attflat logits / weights
__device__ float g_pooled[64 * 640];
__device__ int   g_mask_mode;                // 0=int32, 1=uint8, 2=float32

// ---------------- mask handling ----------------------------------------------
__device__ __forceinline__ bool mask_at(const void* m, size_t idx, int mode) {
    if (mode == 0) return ((const int*)m)[idx] != 0;
    if (mode == 1) return ((const unsigned char*)m)[idx] != 0;
    return ((const float*)m)[idx] != 0.0f;
}

// Scan first n_ints 32-bit words of the mask buffer; classify encoding.
__global__ void detect_mask_kernel(const unsigned int* __restrict__ m, int n_ints) {
    __shared__ int s_i32bad, s_u8bad, s_f32bad;
    if (threadIdx.x == 0) { s_i32bad = 0; s_u8bad = 0; s_f32bad = 0; }
    __syncthreads();
    int i32bad = 0, u8bad = 0, f32bad = 0;
    for (int i = threadIdx.x; i < n_ints; i += blockDim.x) {
        unsigned int v = m[i];
        if (!(v == 0u || v == 1u)) i32bad = 1;
        if ((v & 0xFEFEFEFEu) != 0u) u8bad = 1;
        if (!(v == 0u || v == 0x3F800000u)) f32bad = 1;
    }
    if (i32bad) atomicOr(&s_i32bad, 1);
    if (u8bad)  atomicOr(&s_u8bad, 1);
    if (f32bad) atomicOr(&s_f32bad, 1);
    __syncthreads();
    if (threadIdx.x == 0) {
        int mode;
        if (!s_i32bad)      mode = 0;
        else if (!s_u8bad)  mode = 1;
        else if (!s_f32bad) mode = 2;
        else                mode = 1;   // fallback
        g_mask_mode = mode;
    }
}

// ---------------- reductions ------------------------------------------------
__device__ __forceinline__ float warpReduceMax(float v) {
    #pragma unroll
    for (int o = 16; o > 0; o >>= 1) v = fmaxf(v, __shfl_xor_sync(0xffffffffu, v, o));
    return v;
}
__device__ __forceinline__ float warpReduceSum(float v) {
    #pragma unroll
    for (int o = 16; o > 0; o >>= 1) v += __shfl_xor_sync(0xffffffffu, v, o);
    return v;
}
__device__ __forceinline__ float blockReduceMax(float v) {
    __shared__ float s[32];
    int lane = threadIdx.x & 31, wid = threadIdx.x >> 5;
    v = warpReduceMax(v);
    if (lane == 0) s[wid] = v;
    __syncthreads();
    int nw = (blockDim.x + 31) >> 5;
    v = (threadIdx.x < nw) ? s[threadIdx.x] : -INFINITY;
    if (wid == 0) v = warpReduceMax(v);
    if (threadIdx.x == 0) s[0] = v;
    __syncthreads();
    float r = s[0];
    __syncthreads();
    return r;
}
__device__ __forceinline__ float blockReduceSum(float v) {
    __shared__ float s[32];
    int lane = threadIdx.x & 31, wid = threadIdx.x >> 5;
    v = warpReduceSum(v);
    if (lane == 0) s[wid] = v;
    __syncthreads();
    int nw = (blockDim.x + 31) >> 5;
    v = (threadIdx.x < nw) ? s[threadIdx.x] : 0.0f;
    if (wid == 0) v = warpReduceSum(v);
    if (threadIdx.x == 0) s[0] = v;
    __syncthreads();
    float r = s[0];
    __syncthreads();
    return r;
}

// ---------------- generic tiled GEMM ----------------------------------------
// C[M,N] = A[M,K] * op(B),  op(B) = B^T (B is [N,K]) if TRANSB else B ([K,N]).
constexpr int BM = 128, BN = 128, BK = 16, TM = 8, TN = 8;

template <bool TRANSB>
__global__ __launch_bounds__(256)
void gemm_kernel(const float* __restrict__ A, const float* __restrict__ B,
                 float* __restrict__ C, int M, int N, int K,
                 long sA, long sB, long sC)
{
    __shared__ float As[BK][BM + 4];
    __shared__ float Bs[BK][BN + 4];
    const int bz = blockIdx.z;
    A += (size_t)bz * sA; B += (size_t)bz * sB; C += (size_t)bz * sC;

    const int tid = threadIdx.x;
    const int tx = tid & 15, ty = tid >> 4;
    const int rowBase = blockIdx.y * BM, colBase = blockIdx.x * BN;

    float acc[TM][TN];
    #pragma unroll
    for (int i = 0; i < TM; i++)
        #pragma unroll
        for (int j = 0; j < TN; j++) acc[i][j] = 0.0f;

    for (int k0 = 0; k0 < K; k0 += BK) {
        #pragma unroll
        for (int l = 0; l < 2; ++l) {
            int f = tid + l * 256;          // float4 id 0..511
            int r = f >> 2;
            int c4 = (f & 3) << 2;
            float4 v = *(const float4*)(A + (size_t)(rowBase + r) * K + k0 + c4);
            As[c4 + 0][r] = v.x; As[c4 + 1][r] = v.y;
            As[c4 + 2][r] = v.z; As[c4 + 3][r] = v.w;
        }
        if (TRANSB) {
            #pragma unroll
            for (int l = 0; l < 2; ++l) {
                int f = tid + l * 256;
                int r = f >> 2;
                int c4 = (f & 3) << 2;
                float4 v = *(const float4*)(B + (size_t)(colBase + r) * K + k0 + c4);
                Bs[c4 + 0][r] = v.x; Bs[c4 + 1][r] = v.y;
                Bs[c4 + 2][r] = v.z; Bs[c4 + 3][r] = v.w;
            }
        } else {
            #pragma unroll
            for (int l = 0; l < 2; ++l) {
                int f = tid + l * 256;
                int r = f >> 5;               // 0..15
                int c4 = (f & 31) << 2;       // 0..124
                float4 v = *(const float4*)(B + (size_t)(k0 + r) * N + colBase + c4);
                *(float4*)&Bs[r][c4] = v;
            }
        }
        __syncthreads();

        #pragma unroll
        for (int kk = 0; kk < BK; ++kk) {
            float a[TM], b[TN];
            #pragma unroll
            for (int i = 0; i < TM; i++) a[i] = As[kk][ty * TM + i];
            #pragma unroll
            for (int j = 0; j < TN; j++) b[j] = Bs[kk][tx * TN + j];
            #pragma unroll
            for (int i = 0; i < TM; i++)
                #pragma unroll
                for (int j = 0; j < TN; j++) acc[i][j] += a[i] * b[j];
        }
        __syncthreads();
    }

    #pragma unroll
    for (int i = 0; i < TM; i++) {
        size_t rowOff = (size_t)(rowBase + ty * TM + i) * N + colBase + tx * TN;
        #pragma unroll
        for (int j4 = 0; j4 < TN; j4 += 4) {
            float4 v = make_float4(acc[i][j4], acc[i][j4 + 1], acc[i][j4 + 2], acc[i][j4 + 3]);
            *(float4*)(C + rowOff + j4) = v;
        }
    }
}

// ---------------- fused attflat hidden GEMM ----------------------------------
// att[m] += sum_n relu( (X @ W1)[m,n] + b1[n] ) * w2[n]   (b2 softmax-invariant)
__global__ __launch_bounds__(256)
void fused_hidden_kernel(const float* __restrict__ X, const float* __restrict__ W1,
                         const float* __restrict__ b1, const float* __restrict__ w2,
                         float* __restrict__ attOut, int M, int N, int K)
{
    __shared__ float As[BK][BM + 4];
    __shared__ float Bs[BK][BN + 4];
    __shared__ float partial[BM];

    const int tid = threadIdx.x;
    const int tx = tid & 15, ty = tid >> 4;
    const int rowBase = blockIdx.y * BM, colBase = blockIdx.x * BN;

    float acc[TM][TN];
    #pragma unroll
    for (int i = 0; i < TM; i++)
        #pragma unroll
        for (int j = 0; j < TN; j++) acc[i][j] = 0.0f;

    for (int k0 = 0; k0 < K; k0 += BK) {
        #pragma unroll
        for (int l = 0; l < 2; ++l) {
            int f = tid + l * 256;
            int r = f >> 2;
            int c4 = (f & 3) << 2;
            float4 v = *(const float4*)(X + (size_t)(rowBase + r) * K + k0 + c4);
            As[c4 + 0][r] = v.x; As[c4 + 1][r] = v.y;
            As[c4 + 2][r] = v.z; As[c4 + 3][r] = v.w;
        }
        #pragma unroll
        for (int l = 0; l < 2; ++l) {
            int f = tid + l * 256;
            int r = f >> 5;
            int c4 = (f & 31) << 2;
            float4 v = *(const float4*)(W1 + (size_t)(k0 + r) * N + colBase + c4);
            *(float4*)&Bs[r][c4] = v;
        }
        __syncthreads();

        #pragma unroll
        for (int kk = 0; kk < BK; ++kk) {
            float a[TM], b[TN];
            #pragma unroll
            for (int i = 0; i < TM; i++) a[i] = As[kk][ty * TM + i];
            #pragma unroll
            for (int j = 0; j < TN; j++) b[j] = Bs[kk][tx * TN + j];
            #pragma unroll
            for (int i = 0; i < TM; i++)
                #pragma unroll
                for (int j = 0; j < TN; j++) acc[i][j] += a[i] * b[j];
        }
        __syncthreads();
    }

    float bv[TN], wv[TN];
    #pragma unroll
    for (int j = 0; j < TN; j++) {
        bv[j] = b1[colBase + tx * TN + j];
        wv[j] = w2[colBase + tx * TN + j];
    }
    float rsum[TM];
    #pragma unroll
    for (int i = 0; i < TM; i++) {
        float s = 0.0f;
        #pragma unroll
        for (int j = 0; j < TN; j++) {
            float v = acc[i][j] + bv[j];
            if (v > 0.0f) s += v * wv[j];
        }
        rsum[i] = s;
    }
    if (tid < BM) partial[tid] = 0.0f;
    __syncthreads();
    #pragma unroll
    for (int i = 0; i < TM; i++) atomicAdd(&partial[ty * TM + i], rsum[i]);
    __syncthreads();
    if (tid < BM) atomicAdd(&attOut[rowBase + tid], partial[tid]);
}

// ---------------- softmaxes ---------------------------------------------------
__global__ void attn_softmax_kernel(float* __restrict__ scores,
                                    const void* __restrict__ mask,
                                    int rowsPerBatch, int Nk, float scale)
{
    const int row = blockIdx.x;
    const int b = row / rowsPerBatch;
    const int mode = g_mask_mode;
    float* s = scores + (size_t)row * Nk;

    float lmax = -INFINITY;
    for (int k = threadIdx.x; k < Nk; k += blockDim.x) {
        float v = mask_at(mask, (size_t)b * Nk + k, mode) ? NEGV : s[k] * scale;
        s[k] = v;
        lmax = fmaxf(lmax, v);
    }
    float rmax = blockReduceMax(lmax);

    float lsum = 0.0f;
    for (int k = threadIdx.x; k < Nk; k += blockDim.x) {
        float e = __expf(s[k] - rmax);
        s[k] = e;
        lsum += e;
    }
    float rsum = blockReduceSum(lsum);
    float inv = 1.0f / rsum;
    for (int k = threadIdx.x; k < Nk; k += blockDim.x) s[k] *= inv;
}

__global__ void flat_softmax_kernel(float* __restrict__ att,
                                    const void* __restrict__ mask,
                                    int Nt, float* __restrict__ weightOut)
{
    const int b = blockIdx.x;
    const int mode = g_mask_mode;
    float* a = att + (size_t)b * Nt;

    float lmax = -INFINITY;
    for (int t = threadIdx.x; t < Nt; t += blockDim.x) {
        float v = mask_at(mask, (size_t)b * Nt + t, mode) ? NEGV : a[t];
        a[t] = v;
        lmax = fmaxf(lmax, v);
    }
    float rmax = blockReduceMax(lmax);

    float lsum = 0.0f;
    for (int t = threadIdx.x; t < Nt; t += blockDim.x) {
        float e = __expf(a[t] - rmax);
        a[t] = e;
        lsum += e;
    }
    float rsum = blockReduceSum(lsum);
    float inv = 1.0f / rsum;
    for (int t = threadIdx.x; t < Nt; t += blockDim.x) {
        float p = a[t] * inv;
        a[t] = p;
        if (weightOut) weightOut[(size_t)b * Nt + t] = p;
    }
}

// ---------------- pooled = sum_t att[b,t]*x[b,t,:] ----------------------------
__global__ void pool_kernel(const float* __restrict__ x, const float* __restrict__ att,
                            float* __restrict__ pooled, int Nt)
{
    const int b = blockIdx.x;
    __shared__ float a[512];
    for (int t = threadIdx.x; t < Nt; t += blockDim.x) a[t] = att[(size_t)b * Nt + t];
    __syncthreads();
    const float* xb = x + (size_t)b * Nt * 640;
    for (int d = threadIdx.x; d < 640; d += blockDim.x) {
        float s = 0.0f;
        for (int t = 0; t < Nt; t++) s += a[t] * xb[(size_t)t * 640 + d];
        pooled[(size_t)b * 640 + d] = s;
    }
}

// ---------------- out = pooled @ Wm + bm  (64x640x640) ------------------------
__global__ void final_linear_kernel(const float* __restrict__ pooled,
                                    const float* __restrict__ Wm,
                                    const float* __restrict__ bm,
                                    float* __restrict__ out)
{
    const int b = blockIdx.x;
    __shared__ float p[640];
    for (int i = threadIdx.x; i < 640; i += blockDim.x) p[i] = pooled[(size_t)b * 640 + i];
    __syncthreads();
    for (int n = threadIdx.x; n < 640; n += blockDim.x) {
        float s = bm[n];
        for (int k = 0; k < 640; k++) s += p[k] * Wm[(size_t)k * 640 + n];
        out[(size_t)b * 640 + n] = s;
    }
}

__global__ void zero_kernel(float* __restrict__ p, int n) {
    int i = blockIdx.x * blockDim.x + threadIdx.x;
    if (i < n) p[i] = 0.0f;
}

// ---------------- launch ------------------------------------------------------
extern "C" void kernel_launch(void* const* d_in, const int* in_sizes, int n_in,
                              void* d_out, int out_size)
{
    const float* i_batch = (const float*)d_in[0];   // [64,512,640]
    const float* q_batch = (const float*)d_in[1];   // [64,128,640]
    const void*  i_mask  = d_in[2];                 // [64,512] (dtype auto-detected)
    const void*  q_mask  = d_in[3];                 // [64,128]
    const float* lW1 = (const float*)d_in[4];
    const float* lb1 = (const float*)d_in[5];
    const float* lW2 = (const float*)d_in[6];
    const float* lWm = (const float*)d_in[8];
    const float* lbm = (const float*)d_in[9];
    const float* iW1 = (const float*)d_in[10];
    const float* ib1 = (const float*)d_in[11];
    const float* iW2 = (const float*)d_in[12];
    const float* iWm = (const float*)d_in[14];
    const float* ibm = (const float*)d_in[15];
    float* out = (float*)d_out;                     // i_feat | l_feat | i_weight

    float* scores; float* x; float* att; float* pooled;
    cudaGetSymbolAddress((void**)&scores, g_scores);
    cudaGetSymbolAddress((void**)&x, g_x);
    cudaGetSymbolAddress((void**)&att, g_att);
    cudaGetSymbolAddress((void**)&pooled, g_pooled);

    const float scale = 1.0f / sqrtf(640.0f);
    const int B = 64, Ni = 512, Nq = 128, D = 640, H = 1280;

    // mask dtype detection: scan 8192 ints (32KB), in-bounds for every encoding
    detect_mask_kernel<<<1, 256>>>((const unsigned int*)i_mask, 8192);

    // ===== Phase 1: i_feat path: attn(q=i_batch, k/v=q_batch, mask=q_mask) =====
    gemm_kernel<true><<<dim3(Nq / BN, Ni / BM, B), 256>>>(
        i_batch, q_batch, scores, Ni, Nq, D,
        (long)Ni * D, (long)Nq * D, (long)Ni * Nq);
    attn_softmax_kernel<<<B * Ni, 128>>>(scores, q_mask, Ni, Nq, scale);
    gemm_kernel<false><<<dim3(D / BN, Ni / BM, B), 256>>>(
        scores, q_batch, x, Ni, D, Nq,
        (long)Ni * Nq, (long)Nq * D, (long)Ni * D);

    // ===== Phase 2: attflat(x1, i_mask, lW*) =====
    zero_kernel<<<(B * Ni + 255) / 256, 256>>>(att, B * Ni);
    fused_hidden_kernel<<<dim3(H / BN, (B * Ni) / BM, 1), 256>>>(
        x, lW1, lb1, lW2, att, B * Ni, H, D);
    flat_softmax_kernel<<<B, 256>>>(att, i_mask, Ni, out + 2 * B * D); // i_weight
    pool_kernel<<<B, 256>>>(x, att, pooled, Ni);
    final_linear_kernel<<<B, 256>>>(pooled, lWm, lbm, out);            // i_feat

    // ===== Phase 3: l_feat path: attn(q=q_batch, k/v=i_batch, mask=i_mask) =====
    gemm_kernel<true><<<dim3(Ni / BN, Nq / BM, B), 256>>>(
        q_batch, i_batch, scores, Nq, Ni, D,
        (long)Nq * D, (long)Ni * D, (long)Nq * Ni);
    attn_softmax_kernel<<<B * Nq, 256>>>(scores, i_mask, Nq, Ni, scale);
    gemm_kernel<false><<<dim3(D / BN, Nq / BM, B), 256>>>(
        scores, i_batch, x, Nq, D, Ni,
        (long)Nq * Ni, (long)Ni * D, (long)Nq * D);

    // ===== Phase 4: attflat(x2, q_mask, iW*) =====
    zero_kernel<<<(B * Nq + 255) / 256, 256>>>(att, B * Nq);
    fused_hidden_kernel<<<dim3(H / BN, (B * Nq) / BM, 1), 256>>>(
        x, iW1, ib1, iW2, att, B * Nq, H, D);
    flat_softmax_kernel<<<B, 128>>>(att, q_mask, Nq, nullptr);
    pool_kernel<<<B, 256>>>(x, att, pooled, Nq);
    final_linear_kernel<<<B, 256>>>(pooled, iWm, ibm, out + B * D);    // l_feat
}

// round 3
// speedup vs baseline: 2.0861x; 2.0861x over previous
#include <cuda_runtime.h>
#include <math.h>
#include <stdint.h>

#define NEGV -65504.0f

// ---------------- scratch (device globals; no allocations allowed) ----------
__device__ float g_scores[64 * 512 * 128];
__device__ float g_x[64 * 512 * 640];
__device__ float g_att[64 * 512];
__device__ float g_pooled[64 * 640];
__device__ int   g_mask_mode;                // 0=int32, 1=uint8, 2=float32

// ---------------- mask handling ----------------------------------------------
__device__ __forceinline__ bool mask_at(const void* m, size_t idx, int mode) {
    if (mode == 0) return ((const int*)m)[idx] != 0;
    if (mode == 1) return ((const unsigned char*)m)[idx] != 0;
    return ((const float*)m)[idx] != 0.0f;
}

__global__ void detect_mask_kernel(const unsigned int* __restrict__ m, int n_ints) {
    __shared__ int s_i32bad, s_u8bad, s_f32bad;
    if (threadIdx.x == 0) { s_i32bad = 0; s_u8bad = 0; s_f32bad = 0; }
    __syncthreads();
    int i32bad = 0, u8bad = 0, f32bad = 0;
    for (int i = threadIdx.x; i < n_ints; i += blockDim.x) {
        unsigned int v = m[i];
        if (!(v == 0u || v == 1u)) i32bad = 1;
        if ((v & 0xFEFEFEFEu) != 0u) u8bad = 1;
        if (!(v == 0u || v == 0x3F800000u)) f32bad = 1;
    }
    if (i32bad) atomicOr(&s_i32bad, 1);
    if (u8bad)  atomicOr(&s_u8bad, 1);
    if (f32bad) atomicOr(&s_f32bad, 1);
    __syncthreads();
    if (threadIdx.x == 0) {
        int mode;
        if (!s_i32bad)      mode = 0;
        else if (!s_u8bad)  mode = 1;
        else if (!s_f32bad) mode = 2;
        else                mode = 1;
        g_mask_mode = mode;
    }
}

// ---------------- reductions ------------------------------------------------
__device__ __forceinline__ float warpReduceMax(float v) {
    #pragma unroll
    for (int o = 16; o > 0; o >>= 1) v = fmaxf(v, __shfl_xor_sync(0xffffffffu, v, o));
    return v;
}
__device__ __forceinline__ float warpReduceSum(float v) {
    #pragma unroll
    for (int o = 16; o > 0; o >>= 1) v += __shfl_xor_sync(0xffffffffu, v, o);
    return v;
}
__device__ __forceinline__ float blockReduceMax(float v) {
    __shared__ float s[32];
    int lane = threadIdx.x & 31, wid = threadIdx.x >> 5;
    v = warpReduceMax(v);
    if (lane == 0) s[wid] = v;
    __syncthreads();
    int nw = (blockDim.x + 31) >> 5;
    v = (threadIdx.x < nw) ? s[threadIdx.x] : -INFINITY;
    if (wid == 0) v = warpReduceMax(v);
    if (threadIdx.x == 0) s[0] = v;
    __syncthreads();
    float r = s[0];
    __syncthreads();
    return r;
}
__device__ __forceinline__ float blockReduceSum(float v) {
    __shared__ float s[32];
    int lane = threadIdx.x & 31, wid = threadIdx.x >> 5;
    v = warpReduceSum(v);
    if (lane == 0) s[wid] = v;
    __syncthreads();
    int nw = (blockDim.x + 31) >> 5;
    v = (threadIdx.x < nw) ? s[threadIdx.x] : 0.0f;
    if (wid == 0) v = warpReduceSum(v);
    if (threadIdx.x == 0) s[0] = v;
    __syncthreads();
    float r = s[0];
    __syncthreads();
    return r;
}

// ---------------- TF32 tensor-core GEMM --------------------------------------
// C[M,N] = A[M,K] * op(B). TRANSB: B is [N,K] (B^T applied). Else B is [K,N].
// FUSED: instead of writing C, computes att[m] += sum_n relu(C[m,n]+b1[n])*w2[n].
// Requirements: M%128==0, N%128==0, K%32==0.
constexpr int BM = 128, BN = 128, BK = 32;
constexpr int KS = BK + 4;    // 36: K-major smem row stride (conflict-free frags)
constexpr int NS = BN + 4;    // 132: n-major smem row stride (non-trans B)

__device__ __forceinline__ unsigned f2tf32(float v) {
    unsigned u;
    asm("cvt.rna.tf32.f32 %0, %1;" : "=r"(u) : "f"(v));
    return u;
}

__device__ __forceinline__ void mma_tf32(float* c, const unsigned* a, const unsigned* b) {
    asm volatile(
        "mma.sync.aligned.m16n8k8.row.col.f32.tf32.tf32.f32 "
        "{%0,%1,%2,%3},{%4,%5,%6,%7},{%8,%9},{%0,%1,%2,%3};"
        : "+f"(c[0]), "+f"(c[1]), "+f"(c[2]), "+f"(c[3])
        : "r"(a[0]), "r"(a[1]), "r"(a[2]), "r"(a[3]), "r"(b[0]), "r"(b[1]));
}

template <bool TRANSB, bool FUSED>
__global__ __launch_bounds__(256)
void gemm_tf32_kernel(const float* __restrict__ A, const float* __restrict__ B,
                      float* __restrict__ C, int M, int N, int K,
                      long sA, long sB, long sC,
                      const float* __restrict__ b1, const float* __restrict__ w2)
{
    __shared__ unsigned As[BM][KS];          // [m][k]
    __shared__ unsigned Bs[BN * KS];         // TRANSB: [n][k] stride KS; else [k][n] stride NS

    const int bz = blockIdx.z;
    A += (size_t)bz * sA; B += (size_t)bz * sB; C += (size_t)bz * sC;

    const int tid = threadIdx.x;
    const int lane = tid & 31, wid = tid >> 5;
    const int warp_m = wid & 1, warp_n = wid >> 1;   // 2 x 4 warp grid
    const int wRow = warp_m * 64, wCol = warp_n * 32;
    const int g = lane >> 2, q = lane & 3;
    const int rowBase = blockIdx.y * BM, colBase = blockIdx.x * BN;

    float acc[4][4][4];
    #pragma unroll
    for (int i = 0; i < 4; i++)
        #pragma unroll
        for (int j = 0; j < 4; j++)
            #pragma unroll
            for (int r = 0; r < 4; r++) acc[i][j][r] = 0.0f;

    for (int k0 = 0; k0 < K; k0 += BK) {
        // stage A: 128 rows x 32 k, k contiguous in global
        #pragma unroll
        for (int l = 0; l < 4; ++l) {
            int f = tid + l * 256;
            int r = f >> 3;
            int c4 = (f & 7) << 2;
            float4 v = *(const float4*)(A + (size_t)(rowBase + r) * K + k0 + c4);
            As[r][c4 + 0] = f2tf32(v.x); As[r][c4 + 1] = f2tf32(v.y);
            As[r][c4 + 2] = f2tf32(v.z); As[r][c4 + 3] = f2tf32(v.w);
        }
        // stage B
        if (TRANSB) {
            #pragma unroll
            for (int l = 0; l < 4; ++l) {
                int f = tid + l * 256;
                int r = f >> 3;
                int c4 = (f & 7) << 2;
                float4 v = *(const float4*)(B + (size_t)(colBase + r) * K + k0 + c4);
                unsigned* p = &Bs[r * KS + c4];
                p[0] = f2tf32(v.x); p[1] = f2tf32(v.y);
                p[2] = f2tf32(v.z); p[3] = f2tf32(v.w);
            }
        } else {
            #pragma unroll
            for (int l = 0; l < 4; ++l) {
                int f = tid + l * 256;
                int k = f >> 5;
                int n4 = (f & 31) << 2;
                float4 v = *(const float4*)(B + (size_t)(k0 + k) * N + colBase + n4);
                uint4 u = make_uint4(f2tf32(v.x), f2tf32(v.y), f2tf32(v.z), f2tf32(v.w));
                *(uint4*)&Bs[k * NS + n4] = u;
            }
        }
        __syncthreads();

        #pragma unroll
        for (int ks = 0; ks < 4; ++ks) {
            const int kb = ks * 8;
            unsigned af[4][4];
            #pragma unroll
            for (int mt = 0; mt < 4; mt++) {
                int r0 = wRow + mt * 16 + g;
                af[mt][0] = As[r0][kb + q];
                af[mt][1] = As[r0 + 8][kb + q];
                af[mt][2] = As[r0][kb + 4 + q];
                af[mt][3] = As[r0 + 8][kb + 4 + q];
            }
            unsigned bf[4][2];
            #pragma unroll
            for (int nt = 0; nt < 4; nt++) {
                int c0 = wCol + nt * 8 + g;
                if (TRANSB) {
                    bf[nt][0] = Bs[c0 * KS + kb + q];
                    bf[nt][1] = Bs[c0 * KS + kb + 4 + q];
                } else {
                    bf[nt][0] = Bs[(kb + q) * NS + c0];
                    bf[nt][1] = Bs[(kb + 4 + q) * NS + c0];
                }
            }
            #pragma unroll
            for (int mt = 0; mt < 4; mt++)
                #pragma unroll
                for (int nt = 0; nt < 4; nt++)
                    mma_tf32(acc[mt][nt], af[mt], bf[nt]);
        }
        __syncthreads();
    }

    if (!FUSED) {
        #pragma unroll
        for (int mt = 0; mt < 4; mt++) {
            int row = rowBase + wRow + mt * 16 + g;
            #pragma unroll
            for (int nt = 0; nt < 4; nt++) {
                int col = colBase + wCol + nt * 8 + q * 2;
                *(float2*)(C + (size_t)row * N + col) =
                    make_float2(acc[mt][nt][0], acc[mt][nt][1]);
                *(float2*)(C + (size_t)(row + 8) * N + col) =
                    make_float2(acc[mt][nt][2], acc[mt][nt][3]);
            }
        }
    } else {
        // epilogue: att[row] += sum_col relu(acc + b1[col]) * w2[col]
        float bb[4][2], ww[4][2];
        #pragma unroll
        for (int nt = 0; nt < 4; nt++) {
            int col = colBase + wCol + nt * 8 + q * 2;
            bb[nt][0] = b1[col];     bb[nt][1] = b1[col + 1];
            ww[nt][0] = w2[col];     ww[nt][1] = w2[col + 1];
        }
        #pragma unroll
        for (int mt = 0; mt < 4; mt++) {
            float s0 = 0.0f, s1 = 0.0f;
            #pragma unroll
            for (int nt = 0; nt < 4; nt++) {
                float v;
                v = acc[mt][nt][0] + bb[nt][0]; if (v > 0.0f) s0 += v * ww[nt][0];
                v = acc[mt][nt][1] + bb[nt][1]; if (v > 0.0f) s0 += v * ww[nt][1];
                v = acc[mt][nt][2] + bb[nt][0]; if (v > 0.0f) s1 += v * ww[nt][0];
                v = acc[mt][nt][3] + bb[nt][1]; if (v > 0.0f) s1 += v * ww[nt][1];
            }
            // reduce across the 4 lanes of this row group
            s0 += __shfl_xor_sync(0xffffffffu, s0, 1);
            s0 += __shfl_xor_sync(0xffffffffu, s0, 2);
            s1 += __shfl_xor_sync(0xffffffffu, s1, 1);
            s1 += __shfl_xor_sync(0xffffffffu, s1, 2);
            if (q == 0) {
                int row = rowBase + wRow + mt * 16 + g;
                atomicAdd(&C[row], s0);
                atomicAdd(&C[row + 8], s1);
            }
        }
    }
}

// ---------------- softmaxes ---------------------------------------------------
__global__ void attn_softmax_kernel(float* __restrict__ scores,
                                    const void* __restrict__ mask,
                                    int rowsPerBatch, int Nk, float scale)
{
    const int row = blockIdx.x;
    const int b = row / rowsPerBatch;
    const int mode = g_mask_mode;
    float* s = scores + (size_t)row * Nk;

    float lmax = -INFINITY;
    for (int k = threadIdx.x; k < Nk; k += blockDim.x) {
        float v = mask_at(mask, (size_t)b * Nk + k, mode) ? NEGV : s[k] * scale;
        s[k] = v;
        lmax = fmaxf(lmax, v);
    }
    float rmax = blockReduceMax(lmax);

    float lsum = 0.0f;
    for (int k = threadIdx.x; k < Nk; k += blockDim.x) {
        float e = __expf(s[k] - rmax);
        s[k] = e;
        lsum += e;
    }
    float rsum = blockReduceSum(lsum);
    float inv = 1.0f / rsum;
    for (int k = threadIdx.x; k < Nk; k += blockDim.x) s[k] *= inv;
}

__global__ void flat_softmax_kernel(float* __restrict__ att,
                                    const void* __restrict__ mask,
                                    int Nt, float* __restrict__ weightOut)
{
    const int b = blockIdx.x;
    const int mode = g_mask_mode;
    float* a = att + (size_t)b * Nt;

    float lmax = -INFINITY;
    for (int t = threadIdx.x; t < Nt; t += blockDim.x) {
        float v = mask_at(mask, (size_t)b * Nt + t, mode) ? NEGV : a[t];
        a[t] = v;
        lmax = fmaxf(lmax, v);
    }
    float rmax = blockReduceMax(lmax);

    float lsum = 0.0f;
    for (int t = threadIdx.x; t < Nt; t += blockDim.x) {
        float e = __expf(a[t] - rmax);
        a[t] = e;
        lsum += e;
    }
    float rsum = blockReduceSum(lsum);
    float inv = 1.0f / rsum;
    for (int t = threadIdx.x; t < Nt; t += blockDim.x) {
        float p = a[t] * inv;
        a[t] = p;
        if (weightOut) weightOut[(size_t)b * Nt + t] = p;
    }
}

// ---------------- pooled = sum_t att[b,t]*x[b,t,:] ----------------------------
__global__ void pool_kernel(const float* __restrict__ x, const float* __restrict__ att,
                            float* __restrict__ pooled, int Nt)
{
    const int b = blockIdx.x;
    __shared__ float a[512];
    for (int t = threadIdx.x; t < Nt; t += blockDim.x) a[t] = att[(size_t)b * Nt + t];
    __syncthreads();
    const float* xb = x + (size_t)b * Nt * 640;
    for (int d = threadIdx.x; d < 640; d += blockDim.x) {
        float s = 0.0f;
        for (int t = 0; t < Nt; t++) s += a[t] * xb[(size_t)t * 640 + d];
        pooled[(size_t)b * 640 + d] = s;
    }
}

// ---------------- out = pooled @ Wm + bm  (64x640x640) ------------------------
__global__ void final_linear_kernel(const float* __restrict__ pooled,
                                    const float* __restrict__ Wm,
                                    const float* __restrict__ bm,
                                    float* __restrict__ out)
{
    const int b = blockIdx.x;
    __shared__ float p[640];
    for (int i = threadIdx.x; i < 640; i += blockDim.x) p[i] = pooled[(size_t)b * 640 + i];
    __syncthreads();
    for (int n = threadIdx.x; n < 640; n += blockDim.x) {
        float s = bm[n];
        for (int k = 0; k < 640; k++) s += p[k] * Wm[(size_t)k * 640 + n];
        out[(size_t)b * 640 + n] = s;
    }
}

__global__ void zero_kernel(float* __restrict__ p, int n) {
    int i = blockIdx.x * blockDim.x + threadIdx.x;
    if (i < n) p[i] = 0.0f;
}

// ---------------- launch ------------------------------------------------------
extern "C" void kernel_launch(void* const* d_in, const int* in_sizes, int n_in,
                              void* d_out, int out_size)
{
    const float* i_batch = (const float*)d_in[0];   // [64,512,640]
    const float* q_batch = (const float*)d_in[1];   // [64,128,640]
    const void*  i_mask  = d_in[2];                 // [64,512]
    const void*  q_mask  = d_in[3];                 // [64,128]
    const float* lW1 = (const float*)d_in[4];
    const float* lb1 = (const float*)d_in[5];
    const float* lW2 = (const float*)d_in[6];
    const float* lWm = (const float*)d_in[8];
    const float* lbm = (const float*)d_in[9];
    const float* iW1 = (const float*)d_in[10];
    const float* ib1 = (const float*)d_in[11];
    const float* iW2 = (const float*)d_in[12];
    const float* iWm = (const float*)d_in[14];
    const float* ibm = (const float*)d_in[15];
    float* out = (float*)d_out;                     // i_feat | l_feat | i_weight

    float* scores; float* x; float* att; float* pooled;
    cudaGetSymbolAddress((void**)&scores, g_scores);
    cudaGetSymbolAddress((void**)&x, g_x);
    cudaGetSymbolAddress((void**)&att, g_att);
    cudaGetSymbolAddress((void**)&pooled, g_pooled);

    const float scale = 1.0f / sqrtf(640.0f);
    const int B = 64, Ni = 512, Nq = 128, D = 640, H = 1280;

    detect_mask_kernel<<<1, 256>>>((const unsigned int*)i_mask, 8192);

    // ===== Phase 1: attn(q=i_batch, k/v=q_batch, mask=q_mask) =====
    gemm_tf32_kernel<true, false><<<dim3(Nq / BN, Ni / BM, B), 256>>>(
        i_batch, q_batch, scores, Ni, Nq, D,
        (long)Ni * D, (long)Nq * D, (long)Ni * Nq, nullptr, nullptr);
    attn_softmax_kernel<<<B * Ni, 128>>>(scores, q_mask, Ni, Nq, scale);
    gemm_tf32_kernel<false, false><<<dim3(D / BN, Ni / BM, B), 256>>>(
        scores, q_batch, x, Ni, D, Nq,
        (long)Ni * Nq, (long)Nq * D, (long)Ni * D, nullptr, nullptr);

    // ===== Phase 2: attflat(x1, i_mask, lW*) =====
    zero_kernel<<<(B * Ni + 255) / 256, 256>>>(att, B * Ni);
    gemm_tf32_kernel<false, true><<<dim3(H / BN, (B * Ni) / BM, 1), 256>>>(
        x, lW1, att, B * Ni, H, D, 0, 0, 0, lb1, lW2);
    flat_softmax_kernel<<<B, 256>>>(att, i_mask, Ni, out + 2 * B * D); // i_weight
    pool_kernel<<<B, 256>>>(x, att, pooled, Ni);
    final_linear_kernel<<<B, 256>>>(pooled, lWm, lbm, out);            // i_feat

    // ===== Phase 3: attn(q=q_batch, k/v=i_batch, mask=i_mask) =====
    gemm_tf32_kernel<true, false><<<dim3(Ni / BN, Nq / BM, B), 256>>>(
        q_batch, i_batch, scores, Nq, Ni, D,
        (long)Nq * D, (long)Ni * D, (long)Nq * Ni, nullptr, nullptr);
    attn_softmax_kernel<<<B * Nq, 256>>>(scores, i_mask, Nq, Ni, scale);
    gemm_tf32_kernel<false, false><<<dim3(D / BN, Nq / BM, B), 256>>>(
        scores, i_batch, x, Nq, D, Ni,
        (long)Nq * Ni, (long)Ni * D, (long)Nq * D, nullptr, nullptr);

    // ===== Phase 4: attflat(x2, q_mask, iW*) =====
    zero_kernel<<<(B * Nq + 255) / 256, 256>>>(att, B * Nq);
    gemm_tf32_kernel<false, true><<<dim3(H / BN, (B * Nq) / BM, 1), 256>>>(
        x, iW1, att, B * Nq, H, D, 0, 0, 0, ib1, iW2);
    flat_softmax_kernel<<<B, 128>>>(att, q_mask, Nq, nullptr);
    pool_kernel<<<B, 256>>>(x, att, pooled, Nq);
    final_linear_kernel<<<B, 256>>>(pooled, iWm, ibm, out + B * D);    // l_feat
}

// round 4
// speedup vs baseline: 2.2397x; 1.0736x over previous
#include <cuda_runtime.h>
#include <math.h>
#include <stdint.h>

#define NEGV -65504.0f

// ---------------- scratch (device globals; no allocations allowed) ----------
__device__ float g_scores[64 * 512 * 128];
__device__ float g_x[64 * 512 * 640];
__device__ float g_att[64 * 512];
__device__ float g_pooled[64 * 640];
__device__ int   g_mask_mode;                // 0=int32, 1=uint8, 2=float32

// ---------------- mask handling ----------------------------------------------
__device__ __forceinline__ bool mask_at(const void* m, size_t idx, int mode) {
    if (mode == 0) return ((const int*)m)[idx] != 0;
    if (mode == 1) return ((const unsigned char*)m)[idx] != 0;
    return ((const float*)m)[idx] != 0.0f;
}

__global__ void detect_mask_kernel(const unsigned int* __restrict__ m, int n_ints) {
    __shared__ int s_i32bad, s_u8bad, s_f32bad;
    if (threadIdx.x == 0) { s_i32bad = 0; s_u8bad = 0; s_f32bad = 0; }
    __syncthreads();
    int i32bad = 0, u8bad = 0, f32bad = 0;
    for (int i = threadIdx.x; i < n_ints; i += blockDim.x) {
        unsigned int v = m[i];
        if (!(v == 0u || v == 1u)) i32bad = 1;
        if ((v & 0xFEFEFEFEu) != 0u) u8bad = 1;
        if (!(v == 0u || v == 0x3F800000u)) f32bad = 1;
    }
    if (i32bad) atomicOr(&s_i32bad, 1);
    if (u8bad)  atomicOr(&s_u8bad, 1);
    if (f32bad) atomicOr(&s_f32bad, 1);
    __syncthreads();
    if (threadIdx.x == 0) {
        int mode;
        if (!s_i32bad)      mode = 0;
        else if (!s_u8bad)  mode = 1;
        else if (!s_f32bad) mode = 2;
        else                mode = 1;
        g_mask_mode = mode;
    }
}

// ---------------- reductions ------------------------------------------------
__device__ __forceinline__ float warpReduceMax(float v) {
    #pragma unroll
    for (int o = 16; o > 0; o >>= 1) v = fmaxf(v, __shfl_xor_sync(0xffffffffu, v, o));
    return v;
}
__device__ __forceinline__ float warpReduceSum(float v) {
    #pragma unroll
    for (int o = 16; o > 0; o >>= 1) v += __shfl_xor_sync(0xffffffffu, v, o);
    return v;
}
__device__ __forceinline__ float blockReduceMax(float v) {
    __shared__ float s[32];
    int lane = threadIdx.x & 31, wid = threadIdx.x >> 5;
    v = warpReduceMax(v);
    if (lane == 0) s[wid] = v;
    __syncthreads();
    int nw = (blockDim.x + 31) >> 5;
    v = (threadIdx.x < nw) ? s[threadIdx.x] : -INFINITY;
    if (wid == 0) v = warpReduceMax(v);
    if (threadIdx.x == 0) s[0] = v;
    __syncthreads();
    float r = s[0];
    __syncthreads();
    return r;
}
__device__ __forceinline__ float blockReduceSum(float v) {
    __shared__ float s[32];
    int lane = threadIdx.x & 31, wid = threadIdx.x >> 5;
    v = warpReduceSum(v);
    if (lane == 0) s[wid] = v;
    __syncthreads();
    int nw = (blockDim.x + 31) >> 5;
    v = (threadIdx.x < nw) ? s[threadIdx.x] : 0.0f;
    if (wid == 0) v = warpReduceSum(v);
    if (threadIdx.x == 0) s[0] = v;
    __syncthreads();
    float r = s[0];
    __syncthreads();
    return r;
}

// ---------------- TF32 tensor-core GEMM, cp.async 3-stage pipeline ------------
// C[M,N] = A[M,K] * op(B). TRANSB: B is [N,K]. Else B is [K,N].
// FUSED: att[m] += sum_n relu(C[m,n]+b1[n])*w2[n]  (no C write).
// Requirements: M%128==0, N%128==0, K%32==0, pointers 16B-aligned.
constexpr int BM = 128, BN = 128, BK = 32;
constexpr int KS = 36;               // k-major row stride (floats); 144B, 16B-aligned
constexpr int NS = 132;              // n-major row stride (floats); 528B, 16B-aligned
constexpr int ASZ = BM * KS;         // 4608 floats
constexpr int STAGE_F = 9216;        // A(4608) + B(<=4608) floats per stage
constexpr int STAGES = 3;
constexpr int GEMM_SMEM_BYTES = STAGES * STAGE_F * 4;   // 110592

__device__ __forceinline__ unsigned f2tf32(float v) {
    unsigned u;
    asm("cvt.rna.tf32.f32 %0, %1;" : "=r"(u) : "f"(v));
    return u;
}
__device__ __forceinline__ uint32_t s2u(const void* p) {
    return (uint32_t)__cvta_generic_to_shared(p);
}
__device__ __forceinline__ void cp16(uint32_t s, const void* g) {
    asm volatile("cp.async.cg.shared.global [%0], [%1], 16;" :: "r"(s), "l"(g));
}
__device__ __forceinline__ void cp_commit() {
    asm volatile("cp.async.commit_group;");
}
template <int N> __device__ __forceinline__ void cp_wait() {
    asm volatile("cp.async.wait_group %0;" :: "n"(N));
}

__device__ __forceinline__ void mma_tf32(float* c, const unsigned* a, const unsigned* b) {
    asm volatile(
        "mma.sync.aligned.m16n8k8.row.col.f32.tf32.tf32.f32 "
        "{%0,%1,%2,%3},{%4,%5,%6,%7},{%8,%9},{%0,%1,%2,%3};"
        : "+f"(c[0]), "+f"(c[1]), "+f"(c[2]), "+f"(c[3])
        : "r"(a[0]), "r"(a[1]), "r"(a[2]), "r"(a[3]), "r"(b[0]), "r"(b[1]));
}

template <bool TRANSB, bool FUSED>
__global__ __launch_bounds__(256)
void gemm_tf32_kernel(const float* __restrict__ A, const float* __restrict__ B,
                      float* __restrict__ C, int M, int N, int K,
                      long sA, long sB, long sC,
                      const float* __restrict__ b1, const float* __restrict__ w2)
{
    extern __shared__ float sm[];

    const int bz = blockIdx.z;
    A += (size_t)bz * sA; B += (size_t)bz * sB; C += (size_t)bz * sC;

    const int tid = threadIdx.x;
    const int lane = tid & 31, wid = tid >> 5;
    const int warp_m = wid & 1, warp_n = wid >> 1;   // 2 x 4 warp grid
    const int wRow = warp_m * 64, wCol = warp_n * 32;
    const int g = lane >> 2, q = lane & 3;
    const int rowBase = blockIdx.y * BM, colBase = blockIdx.x * BN;

    // per-thread async-copy coordinates
    const int ar = tid >> 3;              // 0..31 (+32*l)
    const int ac = (tid & 7) << 2;        // 0..28
    const int bkk = tid >> 5;             // 0..7 (+8*l)  (non-trans B)
    const int bn4 = (tid & 31) << 2;      // 0..124

    const int nt = K / BK;

    auto issue = [&](int t) {
        float* As = sm + (t % STAGES) * STAGE_F;
        float* Bs = As + ASZ;
        const int k0 = t * BK;
        #pragma unroll
        for (int l = 0; l < 4; ++l) {
            int r = ar + 32 * l;
            cp16(s2u(As + r * KS + ac), A + (size_t)(rowBase + r) * K + k0 + ac);
        }
        if (TRANSB) {
            #pragma unroll
            for (int l = 0; l < 4; ++l) {
                int r = ar + 32 * l;
                cp16(s2u(Bs + r * KS + ac), B + (size_t)(colBase + r) * K + k0 + ac);
            }
        } else {
            #pragma unroll
            for (int l = 0; l < 4; ++l) {
                int k = bkk + 8 * l;
                cp16(s2u(Bs + k * NS + bn4), B + (size_t)(k0 + k) * N + colBase + bn4);
            }
        }
    };

    float acc[4][4][4];
    #pragma unroll
    for (int i = 0; i < 4; i++)
        #pragma unroll
        for (int j = 0; j < 4; j++)
            #pragma unroll
            for (int r = 0; r < 4; r++) acc[i][j][r] = 0.0f;

    // prologue: 2 tiles in flight
    issue(0); cp_commit();
    if (nt > 1) issue(1);
    cp_commit();

    for (int kt = 0; kt < nt; ++kt) {
        cp_wait<1>();          // tile kt's group complete (commit discipline: 1 group/iter)
        __syncthreads();

        if (kt + 2 < nt) issue(kt + 2);
        cp_commit();

        const float* As = sm + (kt % STAGES) * STAGE_F;
        const float* Bs = As + ASZ;

        #pragma unroll
        for (int ks = 0; ks < 4; ++ks) {
            const int kb = ks * 8;
            unsigned af[4][4];
            #pragma unroll
            for (int mt = 0; mt < 4; mt++) {
                int r0 = wRow + mt * 16 + g;
                af[mt][0] = f2tf32(As[r0 * KS + kb + q]);
                af[mt][1] = f2tf32(As[(r0 + 8) * KS + kb + q]);
                af[mt][2] = f2tf32(As[r0 * KS + kb + 4 + q]);
                af[mt][3] = f2tf32(As[(r0 + 8) * KS + kb + 4 + q]);
            }
            unsigned bf[4][2];
            #pragma unroll
            for (int nt2 = 0; nt2 < 4; nt2++) {
                int c0 = wCol + nt2 * 8 + g;
                if (TRANSB) {
                    bf[nt2][0] = f2tf32(Bs[c0 * KS + kb + q]);
                    bf[nt2][1] = f2tf32(Bs[c0 * KS + kb + 4 + q]);
                } else {
                    bf[nt2][0] = f2tf32(Bs[(kb + q) * NS + c0]);
                    bf[nt2][1] = f2tf32(Bs[(kb + 4 + q) * NS + c0]);
                }
            }
            #pragma unroll
            for (int mt = 0; mt < 4; mt++)
                #pragma unroll
                for (int nt2 = 0; nt2 < 4; nt2++)
                    mma_tf32(acc[mt][nt2], af[mt], bf[nt2]);
        }
    }

    if (!FUSED) {
        #pragma unroll
        for (int mt = 0; mt < 4; mt++) {
            int row = rowBase + wRow + mt * 16 + g;
            #pragma unroll
            for (int nt2 = 0; nt2 < 4; nt2++) {
                int col = colBase + wCol + nt2 * 8 + q * 2;
                *(float2*)(C + (size_t)row * N + col) =
                    make_float2(acc[mt][nt2][0], acc[mt][nt2][1]);
                *(float2*)(C + (size_t)(row + 8) * N + col) =
                    make_float2(acc[mt][nt2][2], acc[mt][nt2][3]);
            }
        }
    } else {
        float bb[4][2], ww[4][2];
        #pragma unroll
        for (int nt2 = 0; nt2 < 4; nt2++) {
            int col = colBase + wCol + nt2 * 8 + q * 2;
            bb[nt2][0] = b1[col];     bb[nt2][1] = b1[col + 1];
            ww[nt2][0] = w2[col];     ww[nt2][1] = w2[col + 1];
        }
        #pragma unroll
        for (int mt = 0; mt < 4; mt++) {
            float s0 = 0.0f, s1 = 0.0f;
            #pragma unroll
            for (int nt2 = 0; nt2 < 4; nt2++) {
                float v;
                v = acc[mt][nt2][0] + bb[nt2][0]; if (v > 0.0f) s0 += v * ww[nt2][0];
                v = acc[mt][nt2][1] + bb[nt2][1]; if (v > 0.0f) s0 += v * ww[nt2][1];
                v = acc[mt][nt2][2] + bb[nt2][0]; if (v > 0.0f) s1 += v * ww[nt2][0];
                v = acc[mt][nt2][3] + bb[nt2][1]; if (v > 0.0f) s1 += v * ww[nt2][1];
            }
            s0 += __shfl_xor_sync(0xffffffffu, s0, 1);
            s0 += __shfl_xor_sync(0xffffffffu, s0, 2);
            s1 += __shfl_xor_sync(0xffffffffu, s1, 1);
            s1 += __shfl_xor_sync(0xffffffffu, s1, 2);
            if (q == 0) {
                int row = rowBase + wRow + mt * 16 + g;
                atomicAdd(&C[row], s0);
                atomicAdd(&C[row + 8], s1);
            }
        }
    }
}

// ---------------- softmaxes ---------------------------------------------------
__global__ void attn_softmax_kernel(float* __restrict__ scores,
                                    const void* __restrict__ mask,
                                    int rowsPerBatch, int Nk, float scale)
{
    const int row = blockIdx.x;
    const int b = row / rowsPerBatch;
    const int mode = g_mask_mode;
    float* s = scores + (size_t)row * Nk;

    float lmax = -INFINITY;
    for (int k = threadIdx.x; k < Nk; k += blockDim.x) {
        float v = mask_at(mask, (size_t)b * Nk + k, mode) ? NEGV : s[k] * scale;
        s[k] = v;
        lmax = fmaxf(lmax, v);
    }
    float rmax = blockReduceMax(lmax);

    float lsum = 0.0f;
    for (int k = threadIdx.x; k < Nk; k += blockDim.x) {
        float e = __expf(s[k] - rmax);
        s[k] = e;
        lsum += e;
    }
    float rsum = blockReduceSum(lsum);
    float inv = 1.0f / rsum;
    for (int k = threadIdx.x; k < Nk; k += blockDim.x) s[k] *= inv;
}

__global__ void flat_softmax_kernel(float* __restrict__ att,
                                    const void* __restrict__ mask,
                                    int Nt, float* __restrict__ weightOut)
{
    const int b = blockIdx.x;
    const int mode = g_mask_mode;
    float* a = att + (size_t)b * Nt;

    float lmax = -INFINITY;
    for (int t = threadIdx.x; t < Nt; t += blockDim.x) {
        float v = mask_at(mask, (size_t)b * Nt + t, mode) ? NEGV : a[t];
        a[t] = v;
        lmax = fmaxf(lmax, v);
    }
    float rmax = blockReduceMax(lmax);

    float lsum = 0.0f;
    for (int t = threadIdx.x; t < Nt; t += blockDim.x) {
        float e = __expf(a[t] - rmax);
        a[t] = e;
        lsum += e;
    }
    float rsum = blockReduceSum(lsum);
    float inv = 1.0f / rsum;
    for (int t = threadIdx.x; t < Nt; t += blockDim.x) {
        float p = a[t] * inv;
        a[t] = p;
        if (weightOut) weightOut[(size_t)b * Nt + t] = p;
    }
}

// ---------------- pooled = sum_t att[b,t]*x[b,t,:] ----------------------------
__global__ void pool_kernel(const float* __restrict__ x, const float* __restrict__ att,
                            float* __restrict__ pooled, int Nt)
{
    const int b = blockIdx.x;
    __shared__ float a[512];
    for (int t = threadIdx.x; t < Nt; t += blockDim.x) a[t] = att[(size_t)b * Nt + t];
    __syncthreads();
    const float* xb = x + (size_t)b * Nt * 640;
    for (int d = threadIdx.x; d < 640; d += blockDim.x) {
        float s = 0.0f;
        for (int t = 0; t < Nt; t++) s += a[t] * xb[(size_t)t * 640 + d];
        pooled[(size_t)b * 640 + d] = s;
    }
}

// ---------------- out = pooled @ Wm + bm  (64x640x640) ------------------------
__global__ void final_linear_kernel(const float* __restrict__ pooled,
                                    const float* __restrict__ Wm,
                                    const float* __restrict__ bm,
                                    float* __restrict__ out)
{
    const int b = blockIdx.x;
    __shared__ float p[640];
    for (int i = threadIdx.x; i < 640; i += blockDim.x) p[i] = pooled[(size_t)b * 640 + i];
    __syncthreads();
    for (int n = threadIdx.x; n < 640; n += blockDim.x) {
        float s = bm[n];
        for (int k = 0; k < 640; k++) s += p[k] * Wm[(size_t)k * 640 + n];
        out[(size_t)b * 640 + n] = s;
    }
}

__global__ void zero_kernel(float* __restrict__ p, int n) {
    int i = blockIdx.x * blockDim.x + threadIdx.x;
    if (i < n) p[i] = 0.0f;
}

// ---------------- launch ------------------------------------------------------
extern "C" void kernel_launch(void* const* d_in, const int* in_sizes, int n_in,
                              void* d_out, int out_size)
{
    const float* i_batch = (const float*)d_in[0];   // [64,512,640]
    const float* q_batch = (const float*)d_in[1];   // [64,128,640]
    const void*  i_mask  = d_in[2];                 // [64,512]
    const void*  q_mask  = d_in[3];                 // [64,128]
    const float* lW1 = (const float*)d_in[4];
    const float* lb1 = (const float*)d_in[5];
    const float* lW2 = (const float*)d_in[6];
    const float* lWm = (const float*)d_in[8];
    const float* lbm = (const float*)d_in[9];
    const float* iW1 = (const float*)d_in[10];
    const float* ib1 = (const float*)d_in[11];
    const float* iW2 = (const float*)d_in[12];
    const float* iWm = (const float*)d_in[14];
    const float* ibm = (const float*)d_in[15];
    float* out = (float*)d_out;                     // i_feat | l_feat | i_weight

    float* scores; float* x; float* att; float* pooled;
    cudaGetSymbolAddress((void**)&scores, g_scores);
    cudaGetSymbolAddress((void**)&x, g_x);
    cudaGetSymbolAddress((void**)&att, g_att);
    cudaGetSymbolAddress((void**)&pooled, g_pooled);

    const float scale = 1.0f / sqrtf(640.0f);
    const int B = 64, Ni = 512, Nq = 128, D = 640, H = 1280;

    cudaFuncSetAttribute(gemm_tf32_kernel<true, false>,
                         cudaFuncAttributeMaxDynamicSharedMemorySize, GEMM_SMEM_BYTES);
    cudaFuncSetAttribute(gemm_tf32_kernel<false, false>,
                         cudaFuncAttributeMaxDynamicSharedMemorySize, GEMM_SMEM_BYTES);
    cudaFuncSetAttribute(gemm_tf32_kernel<false, true>,
                         cudaFuncAttributeMaxDynamicSharedMemorySize, GEMM_SMEM_BYTES);

    detect_mask_kernel<<<1, 256>>>((const unsigned int*)i_mask, 8192);

    // ===== Phase 1: attn(q=i_batch, k/v=q_batch, mask=q_mask) =====
    gemm_tf32_kernel<true, false><<<dim3(Nq / BN, Ni / BM, B), 256, GEMM_SMEM_BYTES>>>(
        i_batch, q_batch, scores, Ni, Nq, D,
        (long)Ni * D, (long)Nq * D, (long)Ni * Nq, nullptr, nullptr);
    attn_softmax_kernel<<<B * Ni, 128>>>(scores, q_mask, Ni, Nq, scale);
    gemm_tf32_kernel<false, false><<<dim3(D / BN, Ni / BM, B), 256, GEMM_SMEM_BYTES>>>(
        scores, q_batch, x, Ni, D, Nq,
        (long)Ni * Nq, (long)Nq * D, (long)Ni * D, nullptr, nullptr);

    // ===== Phase 2: attflat(x1, i_mask, lW*) =====
    zero_kernel<<<(B * Ni + 255) / 256, 256>>>(att, B * Ni);
    gemm_tf32_kernel<false, true><<<dim3(H / BN, (B * Ni) / BM, 1), 256, GEMM_SMEM_BYTES>>>(
        x, lW1, att, B * Ni, H, D, 0, 0, 0, lb1, lW2);
    flat_softmax_kernel<<<B, 256>>>(att, i_mask, Ni, out + 2 * B * D); // i_weight
    pool_kernel<<<B, 256>>>(x, att, pooled, Ni);
    final_linear_kernel<<<B, 256>>>(pooled, lWm, lbm, out);            // i_feat

    // ===== Phase 3: attn(q=q_batch, k/v=i_batch, mask=i_mask) =====
    gemm_tf32_kernel<true, false><<<dim3(Ni / BN, Nq / BM, B), 256, GEMM_SMEM_BYTES>>>(
        q_batch, i_batch, scores, Nq, Ni, D,
        (long)Nq * D, (long)Ni * D, (long)Nq * Ni, nullptr, nullptr);
    attn_softmax_kernel<<<B * Nq, 256>>>(scores, i_mask, Nq, Ni, scale);
    gemm_tf32_kernel<false, false><<<dim3(D / BN, Nq / BM, B), 256, GEMM_SMEM_BYTES>>>(
        scores, i_batch, x, Nq, D, Ni,
        (long)Nq * Ni, (long)Ni * D, (long)Nq * D, nullptr, nullptr);

    // ===== Phase 4: attflat(x2, q_mask, iW*) =====
    zero_kernel<<<(B * Nq + 255) / 256, 256>>>(att, B * Nq);
    gemm_tf32_kernel<false, true><<<dim3(H / BN, (B * Nq) / BM, 1), 256, GEMM_SMEM_BYTES>>>(
        x, iW1, att, B * Nq, H, D, 0, 0, 0, ib1, iW2);
    flat_softmax_kernel<<<B, 128>>>(att, q_mask, Nq, nullptr);
    pool_kernel<<<B, 256>>>(x, att, pooled, Nq);
    final_linear_kernel<<<B, 256>>>(pooled, iWm, ibm, out + B * D);    // l_feat
}

// round 6
// speedup vs baseline: 2.5040x; 1.1180x over previous
#include <cuda_runtime.h>
#include <cuda_fp16.h>
#include <math.h>
#include <stdint.h>

#define NEGV -65504.0f

// ---------------- scratch (device globals; no allocations allowed) ----------
__device__ float  g_scores[64 * 512 * 128];     // QK f32 out (reused both phases)
__device__ __half g_scores_h[64 * 512 * 128];   // softmaxed scores, half
__device__ float  g_x[64 * 512 * 640];          // attention out f32 (for pool)
__device__ __half g_x_h[64 * 512 * 640];        // attention out half (GEMM A)
__device__ __half g_i_h[64 * 512 * 640];        // half(i_batch)
__device__ __half g_q_h[64 * 128 * 640];        // half(q_batch)
__device__ __half g_vT1[64 * 640 * 128];        // transpose(q_batch) half
__device__ __half g_iT[64 * 640 * 512];         // transpose(i_batch) half
__device__ __half g_w1t[1280 * 640];            // lW1^T half
__device__ __half g_iw1t[1280 * 640];           // iW1^T half
__device__ float  g_att[64 * 512];
__device__ float  g_pooled[64 * 640];
__device__ int    g_mask_mode;                  // 0=int32, 1=uint8, 2=float32

// ---------------- helpers ------------------------------------------------------
__device__ __forceinline__ uint32_t s2u(const void* p) {
    return (uint32_t)__cvta_generic_to_shared(p);
}
__device__ __forceinline__ void cp16(uint32_t s, const void* g) {
    asm volatile("cp.async.cg.shared.global [%0], [%1], 16;" :: "r"(s), "l"(g));
}
__device__ __forceinline__ void cp_commit() { asm volatile("cp.async.commit_group;"); }
template <int N> __device__ __forceinline__ void cp_wait() {
    asm volatile("cp.async.wait_group %0;" :: "n"(N));
}

__device__ __forceinline__ void mma_f16(float* c, const uint32_t* a, const uint32_t* b) {
    asm volatile(
        "mma.sync.aligned.m16n8k16.row.col.f32.f16.f16.f32 "
        "{%0,%1,%2,%3},{%4,%5,%6,%7},{%8,%9},{%0,%1,%2,%3};"
        : "+f"(c[0]), "+f"(c[1]), "+f"(c[2]), "+f"(c[3])
        : "r"(a[0]), "r"(a[1]), "r"(a[2]), "r"(a[3]), "r"(b[0]), "r"(b[1]));
}

// ---------------- mask handling ------------------------------------------------
__device__ __forceinline__ bool mask_at(const void* m, size_t idx, int mode) {
    if (mode == 0) return ((const int*)m)[idx] != 0;
    if (mode == 1) return ((const unsigned char*)m)[idx] != 0;
    return ((const float*)m)[idx] != 0.0f;
}

__global__ void detect_mask_kernel(const unsigned int* __restrict__ m, int n_ints) {
    __shared__ int s_i32bad, s_u8bad, s_f32bad;
    if (threadIdx.x == 0) { s_i32bad = 0; s_u8bad = 0; s_f32bad = 0; }
    __syncthreads();
    int i32bad = 0, u8bad = 0, f32bad = 0;
    for (int i = threadIdx.x; i < n_ints; i += blockDim.x) {
        unsigned int v = m[i];
        if (!(v == 0u || v == 1u)) i32bad = 1;
        if ((v & 0xFEFEFEFEu) != 0u) u8bad = 1;
        if (!(v == 0u || v == 0x3F800000u)) f32bad = 1;
    }
    if (i32bad) atomicOr(&s_i32bad, 1);
    if (u8bad)  atomicOr(&s_u8bad, 1);
    if (f32bad) atomicOr(&s_f32bad, 1);
    __syncthreads();
    if (threadIdx.x == 0) {
        int mode;
        if (!s_i32bad)      mode = 0;
        else if (!s_u8bad)  mode = 1;
        else if (!s_f32bad) mode = 2;
        else                mode = 1;
        g_mask_mode = mode;
    }
}

// ---------------- reductions ---------------------------------------------------
__device__ __forceinline__ float warpReduceMax(float v) {
    #pragma unroll
    for (int o = 16; o > 0; o >>= 1) v = fmaxf(v, __shfl_xor_sync(0xffffffffu, v, o));
    return v;
}
__device__ __forceinline__ float warpReduceSum(float v) {
    #pragma unroll
    for (int o = 16; o > 0; o >>= 1) v += __shfl_xor_sync(0xffffffffu, v, o);
    return v;
}
__device__ __forceinline__ float blockReduceMax(float v) {
    __shared__ float s[32];
    int lane = threadIdx.x & 31, wid = threadIdx.x >> 5;
    v = warpReduceMax(v);
    if (lane == 0) s[wid] = v;
    __syncthreads();
    int nw = (blockDim.x + 31) >> 5;
    v = (threadIdx.x < nw) ? s[threadIdx.x] : -INFINITY;
    if (wid == 0) v = warpReduceMax(v);
    if (threadIdx.x == 0) s[0] = v;
    __syncthreads();
    float r = s[0];
    __syncthreads();
    return r;
}
__device__ __forceinline__ float blockReduceSum(float v) {
    __shared__ float s[32];
    int lane = threadIdx.x & 31, wid = threadIdx.x >> 5;
    v = warpReduceSum(v);
    if (lane == 0) s[wid] = v;
    __syncthreads();
    int nw = (blockDim.x + 31) >> 5;
    v = (threadIdx.x < nw) ? s[threadIdx.x] : 0.0f;
    if (wid == 0) v = warpReduceSum(v);
    if (threadIdx.x == 0) s[0] = v;
    __syncthreads();
    float r = s[0];
    __syncthreads();
    return r;
}

// ---------------- FP16 tensor-core GEMM, cp.async 4-stage -----------------------
// C[M,N] = A[M,K] @ B[N,K]^T, both half, K-major. 128x128 CTA tile, BK=32.
// EPI: 0 = store f32 C; 1 = store f32 C + half Ch; 2 = fused attflat epilogue.
// Requirements: M%128==0, N%128==0, K%32==0, nt=K/32 >= 3.
constexpr int RSH = 40;                       // row stride in halfs (80B, 16B aligned)
constexpr int TILEH = 128 * RSH;              // halfs per operand tile
constexpr int STAGEH = 2 * TILEH;             // A + B
constexpr int H16_STAGES = 4;
constexpr int H16_SMEM = H16_STAGES * STAGEH * 2;   // 81920 bytes

template <int EPI>
__global__ __launch_bounds__(256, 2)
void gemm_h16(const __half* __restrict__ A, const __half* __restrict__ B,
              float* __restrict__ C, __half* __restrict__ Ch,
              int M, int N, int K, long sA, long sB, long sC,
              const float* __restrict__ b1, const float* __restrict__ w2)
{
    extern __shared__ __half sm[];

    const int bz = blockIdx.z;
    A += (size_t)bz * sA; B += (size_t)bz * sB;
    C += (size_t)bz * sC;
    if (EPI == 1) Ch += (size_t)bz * sC;

    const int tid = threadIdx.x;
    const int lane = tid & 31, wid = tid >> 5;
    const int warp_m = wid & 1, warp_n = wid >> 1;   // 2 x 4 warps
    const int wRow = warp_m * 64, wCol = warp_n * 32;
    const int g = lane >> 2, q = lane & 3;
    const int rowBase = blockIdx.y * 128, colBase = blockIdx.x * 128;

    // copy coords: 512 chunks of 16B per operand tile, 2 per thread
    const int cr = tid >> 1;             // 0..127 row
    const int cc = (tid & 1) << 4;       // 0 or 16 (halfs); +8 within via 2 chunks
    const int nt = K / 32;

    auto issue = [&](int t) {
        __half* st = sm + (t % H16_STAGES) * STAGEH;
        __half* As = st;
        __half* Bs = st + TILEH;
        const __half* Ag = A + (size_t)rowBase * K + t * 32;
        const __half* Bg = B + (size_t)colBase * K + t * 32;
        // each thread: 2 chunks A + 2 chunks B (16B = 8 halfs each)
        cp16(s2u(As + cr * RSH + cc),     Ag + (size_t)cr * K + cc);
        cp16(s2u(As + cr * RSH + cc + 8), Ag + (size_t)cr * K + cc + 8);
        cp16(s2u(Bs + cr * RSH + cc),     Bg + (size_t)cr * K + cc);
        cp16(s2u(Bs + cr * RSH + cc + 8), Bg + (size_t)cr * K + cc + 8);
    };

    float acc[4][4][4];
    #pragma unroll
    for (int i = 0; i < 4; i++)
        #pragma unroll
        for (int j = 0; j < 4; j++)
            #pragma unroll
            for (int r = 0; r < 4; r++) acc[i][j][r] = 0.0f;

    issue(0); cp_commit();
    issue(1); cp_commit();
    issue(2); cp_commit();

    for (int kt = 0; kt < nt; ++kt) {
        cp_wait<2>();
        __syncthreads();
        if (kt + 3 < nt) issue(kt + 3);
        cp_commit();

        const __half* st = sm + (kt % H16_STAGES) * STAGEH;
        const __half* As = st;
        const __half* Bs = st + TILEH;

        #pragma unroll
        for (int ks = 0; ks < 2; ++ks) {
            const int kb = ks * 16;
            uint32_t af[4][4];
            #pragma unroll
            for (int mt = 0; mt < 4; mt++) {
                int r0 = wRow + mt * 16 + g;
                af[mt][0] = *(const uint32_t*)(As + r0 * RSH + kb + 2 * q);
                af[mt][1] = *(const uint32_t*)(As + (r0 + 8) * RSH + kb + 2 * q);
                af[mt][2] = *(const uint32_t*)(As + r0 * RSH + kb + 8 + 2 * q);
                af[mt][3] = *(const uint32_t*)(As + (r0 + 8) * RSH + kb + 8 + 2 * q);
            }
            uint32_t bf[4][2];
            #pragma unroll
            for (int nn = 0; nn < 4; nn++) {
                int c0 = wCol + nn * 8 + g;
                bf[nn][0] = *(const uint32_t*)(Bs + c0 * RSH + kb + 2 * q);
                bf[nn][1] = *(const uint32_t*)(Bs + c0 * RSH + kb + 8 + 2 * q);
            }
            #pragma unroll
            for (int mt = 0; mt < 4; mt++)
                #pragma unroll
                for (int nn = 0; nn < 4; nn++)
                    mma_f16(acc[mt][nn], af[mt], bf[nn]);
        }
    }

    if (EPI == 2) {
        // att[row] += sum_col relu(acc + b1[col]) * w2[col]
        float bb[4][2], ww[4][2];
        #pragma unroll
        for (int nn = 0; nn < 4; nn++) {
            int col = colBase + wCol + nn * 8 + 2 * q;
            bb[nn][0] = b1[col];     bb[nn][1] = b1[col + 1];
            ww[nn][0] = w2[col];     ww[nn][1] = w2[col + 1];
        }
        #pragma unroll
        for (int mt = 0; mt < 4; mt++) {
            float s0 = 0.0f, s1 = 0.0f;
            #pragma unroll
            for (int nn = 0; nn < 4; nn++) {
                float v;
                v = acc[mt][nn][0] + bb[nn][0]; if (v > 0.0f) s0 += v * ww[nn][0];
                v = acc[mt][nn][1] + bb[nn][1]; if (v > 0.0f) s0 += v * ww[nn][1];
                v = acc[mt][nn][2] + bb[nn][0]; if (v > 0.0f) s1 += v * ww[nn][0];
                v = acc[mt][nn][3] + bb[nn][1]; if (v > 0.0f) s1 += v * ww[nn][1];
            }
            s0 += __shfl_xor_sync(0xffffffffu, s0, 1);
            s0 += __shfl_xor_sync(0xffffffffu, s0, 2);
            s1 += __shfl_xor_sync(0xffffffffu, s1, 1);
            s1 += __shfl_xor_sync(0xffffffffu, s1, 2);
            if (q == 0) {
                int row = rowBase + wRow + mt * 16 + g;
                atomicAdd(&C[row], s0);
                atomicAdd(&C[row + 8], s1);
            }
        }
    } else {
        #pragma unroll
        for (int mt = 0; mt < 4; mt++) {
            int row = rowBase + wRow + mt * 16 + g;
            #pragma unroll
            for (int nn = 0; nn < 4; nn++) {
                int col = colBase + wCol + nn * 8 + 2 * q;
                float2 lo = make_float2(acc[mt][nn][0], acc[mt][nn][1]);
                float2 hi = make_float2(acc[mt][nn][2], acc[mt][nn][3]);
                *(float2*)(C + (size_t)row * N + col) = lo;
                *(float2*)(C + (size_t)(row + 8) * N + col) = hi;
                if (EPI == 1) {
                    *(__half2*)(Ch + (size_t)row * N + col) =
                        __floats2half2_rn(lo.x, lo.y);
                    *(__half2*)(Ch + (size_t)(row + 8) * N + col) =
                        __floats2half2_rn(hi.x, hi.y);
                }
            }
        }
    }
}

// ---------------- conversions ----------------------------------------------------
__global__ void f2h_kernel(const float* __restrict__ in, __half* __restrict__ out,
                           int n2)   // n2 = n/2
{
    int i = blockIdx.x * blockDim.x + threadIdx.x;
    if (i < n2) {
        float2 v = ((const float2*)in)[i];
        ((__half2*)out)[i] = __floats2half2_rn(v.x, v.y);
    }
}

// in f32 [z][R][C] -> out half [z][C][R]
__global__ void transpose_f2h_kernel(const float* __restrict__ in,
                                     __half* __restrict__ out, int R, int C)
{
    __shared__ float t[32][33];
    const size_t zo = (size_t)blockIdx.z * R * C;
    const int c0 = blockIdx.x * 32, r0 = blockIdx.y * 32;
    #pragma unroll
    for (int i = threadIdx.y; i < 32; i += 8)
        t[i][threadIdx.x] = in[zo + (size_t)(r0 + i) * C + c0 + threadIdx.x];
    __syncthreads();
    #pragma unroll
    for (int i = threadIdx.y; i < 32; i += 8)
        out[zo + (size_t)(c0 + i) * R + r0 + threadIdx.x] =
            __float2half_rn(t[threadIdx.x][i]);
}

// ---------------- softmaxes -------------------------------------------------------
// reads f32 scores, writes HALF probabilities. VPT = Nk/128 <= 4, block 128.
__global__ void attn_softmax_h(const float* __restrict__ scores,
                               __half* __restrict__ outh,
                               const void* __restrict__ mask,
                               int rowsPerBatch, int Nk, float scale)
{
    const int row = blockIdx.x;
    const int b = row / rowsPerBatch;
    const int mode = g_mask_mode;
    const float* s = scores + (size_t)row * Nk;
    __half* o = outh + (size_t)row * Nk;
    const int vpt = Nk >> 7;            // 1 or 4

    float v[4];
    float lmax = -INFINITY;
    for (int j = 0; j < vpt; ++j) {
        int k = threadIdx.x + (j << 7);
        float x = mask_at(mask, (size_t)b * Nk + k, mode) ? NEGV : s[k] * scale;
        v[j] = x;
        lmax = fmaxf(lmax, x);
    }
    float rmax = blockReduceMax(lmax);
    float lsum = 0.0f;
    for (int j = 0; j < vpt; ++j) {
        v[j] = __expf(v[j] - rmax);
        lsum += v[j];
    }
    float inv = 1.0f / blockReduceSum(lsum);
    for (int j = 0; j < vpt; ++j) {
        int k = threadIdx.x + (j << 7);
        o[k] = __float2half_rn(v[j] * inv);
    }
}

__global__ void flat_softmax_kernel(float* __restrict__ att,
                                    const void* __restrict__ mask,
                                    int Nt, float* __restrict__ weightOut)
{
    const int b = blockIdx.x;
    const int mode = g_mask_mode;
    float* a = att + (size_t)b * Nt;

    float lmax = -INFINITY;
    for (int t = threadIdx.x; t < Nt; t += blockDim.x) {
        float v = mask_at(mask, (size_t)b * Nt + t, mode) ? NEGV : a[t];
        a[t] = v;
        lmax = fmaxf(lmax, v);
    }
    float rmax = blockReduceMax(lmax);
    float lsum = 0.0f;
    for (int t = threadIdx.x; t < Nt; t += blockDim.x) {
        float e = __expf(a[t] - rmax);
        a[t] = e;
        lsum += e;
    }
    float inv = 1.0f / blockReduceSum(lsum);
    for (int t = threadIdx.x; t < Nt; t += blockDim.x) {
        float p = a[t] * inv;
        a[t] = p;
        if (weightOut) weightOut[(size_t)b * Nt + t] = p;
    }
}

// ---------------- pooled = sum_t att[b,t]*x[b,t,:] --------------------------------
__global__ void pool_kernel(const float* __restrict__ x, const float* __restrict__ att,
                            float* __restrict__ pooled, int Nt)
{
    const int b = blockIdx.x;
    const int d = blockIdx.y * 128 + threadIdx.x;
    __shared__ float a[512];
    for (int t = threadIdx.x; t < Nt; t += blockDim.x) a[t] = att[(size_t)b * Nt + t];
    __syncthreads();
    const float* xb = x + (size_t)b * Nt * 640;
    float s = 0.0f;
    for (int t = 0; t < Nt; t++) s += a[t] * xb[(size_t)t * 640 + d];
    pooled[(size_t)b * 640 + d] = s;
}

// ---------------- out = pooled @ Wm + bm  (64x640x640) ----------------------------
__global__ void final_linear_kernel(const float* __restrict__ pooled,
                                    const float* __restrict__ Wm,
                                    const float* __restrict__ bm,
                                    float* __restrict__ out)
{
    const int b = blockIdx.x;
    const int n = blockIdx.y * 128 + threadIdx.x;
    __shared__ float p[640];
    for (int i = threadIdx.x; i < 640; i += blockDim.x) p[i] = pooled[(size_t)b * 640 + i];
    __syncthreads();
    float s = bm[n];
    for (int k = 0; k < 640; k++) s += p[k] * Wm[(size_t)k * 640 + n];
    out[(size_t)b * 640 + n] = s;
}

__global__ void zero_kernel(float* __restrict__ p, int n) {
    int i = blockIdx.x * blockDim.x + threadIdx.x;
    if (i < n) p[i] = 0.0f;
}

// ---------------- launch ------------------------------------------------------------
extern "C" void kernel_launch(void* const* d_in, const int* in_sizes, int n_in,
                              void* d_out, int out_size)
{
    const float* i_batch = (const float*)d_in[0];   // [64,512,640]
    const float* q_batch = (const float*)d_in[1];   // [64,128,640]
    const void*  i_mask  = d_in[2];                 // [64,512]
    const void*  q_mask  = d_in[3];                 // [64,128]
    const float* lW1 = (const float*)d_in[4];
    const float* lb1 = (const float*)d_in[5];
    const float* lW2 = (const float*)d_in[6];
    const float* lWm = (const float*)d_in[8];
    const float* lbm = (const float*)d_in[9];
    const float* iW1 = (const float*)d_in[10];
    const float* ib1 = (const float*)d_in[11];
    const float* iW2 = (const float*)d_in[12];
    const float* iWm = (const float*)d_in[14];
    const float* ibm = (const float*)d_in[15];
    float* out = (float*)d_out;                     // i_feat | l_feat | i_weight

    float *scores, *x, *att, *pooled;
    __half *scores_h, *x_h, *i_h, *q_h, *vT1, *iT, *w1t, *iw1t;
    cudaGetSymbolAddress((void**)&scores, g_scores);
    cudaGetSymbolAddress((void**)&scores_h, g_scores_h);
    cudaGetSymbolAddress((void**)&x, g_x);
    cudaGetSymbolAddress((void**)&x_h, g_x_h);
    cudaGetSymbolAddress((void**)&i_h, g_i_h);
    cudaGetSymbolAddress((void**)&q_h, g_q_h);
    cudaGetSymbolAddress((void**)&vT1, g_vT1);
    cudaGetSymbolAddress((void**)&iT, g_iT);
    cudaGetSymbolAddress((void**)&w1t, g_w1t);
    cudaGetSymbolAddress((void**)&iw1t, g_iw1t);
    cudaGetSymbolAddress((void**)&att, g_att);
    cudaGetSymbolAddress((void**)&pooled, g_pooled);

    const float scale = 1.0f / sqrtf(640.0f);
    const int B = 64, Ni = 512, Nq = 128, D = 640, H = 1280;

    cudaFuncSetAttribute(gemm_h16<0>, cudaFuncAttributeMaxDynamicSharedMemorySize, H16_SMEM);
    cudaFuncSetAttribute(gemm_h16<1>, cudaFuncAttributeMaxDynamicSharedMemorySize, H16_SMEM);
    cudaFuncSetAttribute(gemm_h16<2>, cudaFuncAttributeMaxDynamicSharedMemorySize, H16_SMEM);

    detect_mask_kernel<<<1, 256>>>((const unsigned int*)i_mask, 8192);

    // ---- prep: conversions + transposes (all independent) ----
    f2h_kernel<<<(B * Ni * D / 2 + 255) / 256, 256>>>(i_batch, i_h, B * Ni * D / 2);
    f2h_kernel<<<(B * Nq * D / 2 + 255) / 256, 256>>>(q_batch, q_h, B * Nq * D / 2);
    transpose_f2h_kernel<<<dim3(D / 32, Nq / 32, B), dim3(32, 8)>>>(q_batch, vT1, Nq, D);
    transpose_f2h_kernel<<<dim3(D / 32, Ni / 32, B), dim3(32, 8)>>>(i_batch, iT, Ni, D);
    transpose_f2h_kernel<<<dim3(H / 32, D / 32, 1), dim3(32, 8)>>>(lW1, w1t, D, H);
    transpose_f2h_kernel<<<dim3(H / 32, D / 32, 1), dim3(32, 8)>>>(iW1, iw1t, D, H);

    // ===== Phase 1: attn(q=i_batch, k/v=q_batch, mask=q_mask) =====
    gemm_h16<0><<<dim3(1, 4, B), 256, H16_SMEM>>>(
        i_h, q_h, scores, nullptr, Ni, Nq, D,
        (long)Ni * D, (long)Nq * D, (long)Ni * Nq, nullptr, nullptr);
    attn_softmax_h<<<B * Ni, 128>>>(scores, scores_h, q_mask, Ni, Nq, scale);
    gemm_h16<1><<<dim3(5, 4, B), 256, H16_SMEM>>>(
        scores_h, vT1, x, x_h, Ni, D, Nq,
        (long)Ni * Nq, (long)D * Nq, (long)Ni * D, nullptr, nullptr);

    // ===== Phase 2: attflat(x1, i_mask, lW*) =====
    zero_kernel<<<(B * Ni + 255) / 256, 256>>>(att, B * Ni);
    gemm_h16<2><<<dim3(H / 128, (B * Ni) / 128, 1), 256, H16_SMEM>>>(
        x_h, w1t, att, nullptr, B * Ni, H, D, 0, 0, 0, lb1, lW2);
    flat_softmax_kernel<<<B, 256>>>(att, i_mask, Ni, out + 2 * B * D);   // i_weight
    pool_kernel<<<dim3(B, 5), 128>>>(x, att, pooled, Ni);
    final_linear_kernel<<<dim3(B, 5), 128>>>(pooled, lWm, lbm, out);     // i_feat

    // ===== Phase 3: attn(q=q_batch, k/v=i_batch, mask=i_mask) =====
    gemm_h16<0><<<dim3(4, 1, B), 256, H16_SMEM>>>(
        q_h, i_h, scores, nullptr, Nq, Ni, D,
        (long)Nq * D, (long)Ni * D, (long)Nq * Ni, nullptr, nullptr);
    attn_softmax_h<<<B * Nq, 128>>>(scores, scores_h, i_mask, Nq, Ni, scale);
    gemm_h16<1><<<dim3(5, 1, B), 256, H16_SMEM>>>(
        scores_h, iT, x, x_h, Nq, D, Ni,
        (long)Nq * Ni, (long)D * Ni, (long)Nq * D, nullptr, nullptr);

    // ===== Phase 4: attflat(x2, q_mask, iW*) =====
    zero_kernel<<<(B * Nq + 255) / 256, 256>>>(att, B * Nq);
    gemm_h16<2><<<dim3(H / 128, (B * Nq) / 128, 1), 256, H16_SMEM>>>(
        x_h, iw1t, att, nullptr, B * Nq, H, D, 0, 0, 0, ib1, iW2);
    flat_softmax_kernel<<<B, 128>>>(att, q_mask, Nq, nullptr);
    pool_kernel<<<dim3(B, 5), 128>>>(x, att, pooled, Nq);
    final_linear_kernel<<<dim3(B, 5), 128>>>(pooled, iWm, ibm, out + B * D);  // l_feat
}

// round 7
// speedup vs baseline: 2.8294x; 1.1300x over previous
#include <cuda_runtime.h>
#include <cuda_fp16.h>
#include <math.h>
#include <stdint.h>

#define NEGV -65504.0f

// ---------------- scratch (device globals; no allocations allowed) ----------
__device__ float  g_scores[64 * 512 * 128];     // QK f32 out (reused both phases)
__device__ __half g_scores_h[64 * 512 * 128];   // softmaxed scores, half
__device__ __half g_x_h[64 * 512 * 640];        // attention out half
__device__ __half g_i_h[64 * 512 * 640];        // half(i_batch)
__device__ __half g_q_h[64 * 128 * 640];        // half(q_batch)
__device__ __half g_vT1[64 * 640 * 128];        // transpose(q_batch) half
__device__ __half g_iT[64 * 640 * 512];         // transpose(i_batch) half
__device__ __half g_w1t[1280 * 640];            // lW1^T half
__device__ __half g_iw1t[1280 * 640];           // iW1^T half
__device__ float  g_att[64 * 512];
__device__ float  g_pooled[64 * 640];
__device__ int    g_mask_mode;                  // 0=int32, 1=uint8, 2=float32

// ---------------- helpers ------------------------------------------------------
__device__ __forceinline__ uint32_t s2u(const void* p) {
    return (uint32_t)__cvta_generic_to_shared(p);
}
__device__ __forceinline__ void cp16(uint32_t s, const void* g) {
    asm volatile("cp.async.cg.shared.global [%0], [%1], 16;" :: "r"(s), "l"(g));
}
__device__ __forceinline__ void cp_commit() { asm volatile("cp.async.commit_group;"); }
template <int N> __device__ __forceinline__ void cp_wait() {
    asm volatile("cp.async.wait_group %0;" :: "n"(N));
}
__device__ __forceinline__ void ldsm_x4(uint32_t& r0, uint32_t& r1, uint32_t& r2,
                                        uint32_t& r3, uint32_t addr) {
    asm volatile("ldmatrix.sync.aligned.m8n8.x4.shared.b16 {%0,%1,%2,%3}, [%4];"
                 : "=r"(r0), "=r"(r1), "=r"(r2), "=r"(r3) : "r"(addr));
}
__device__ __forceinline__ void mma_f16(float* c, const uint32_t* a, const uint32_t* b) {
    asm volatile(
        "mma.sync.aligned.m16n8k16.row.col.f32.f16.f16.f32 "
        "{%0,%1,%2,%3},{%4,%5,%6,%7},{%8,%9},{%0,%1,%2,%3};"
        : "+f"(c[0]), "+f"(c[1]), "+f"(c[2]), "+f"(c[3])
        : "r"(a[0]), "r"(a[1]), "r"(a[2]), "r"(a[3]), "r"(b[0]), "r"(b[1]));
}

// ---------------- mask handling ------------------------------------------------
__device__ __forceinline__ bool mask_at(const void* m, size_t idx, int mode) {
    if (mode == 0) return ((const int*)m)[idx] != 0;
    if (mode == 1) return ((const unsigned char*)m)[idx] != 0;
    return ((const float*)m)[idx] != 0.0f;
}

__global__ void detect_mask_kernel(const unsigned int* __restrict__ m, int n_ints) {
    __shared__ int s_i32bad, s_u8bad, s_f32bad;
    if (threadIdx.x == 0) { s_i32bad = 0; s_u8bad = 0; s_f32bad = 0; }
    __syncthreads();
    int i32bad = 0, u8bad = 0, f32bad = 0;
    for (int i = threadIdx.x; i < n_ints; i += blockDim.x) {
        unsigned int v = m[i];
        if (!(v == 0u || v == 1u)) i32bad = 1;
        if ((v & 0xFEFEFEFEu) != 0u) u8bad = 1;
        if (!(v == 0u || v == 0x3F800000u)) f32bad = 1;
    }
    if (i32bad) atomicOr(&s_i32bad, 1);
    if (u8bad)  atomicOr(&s_u8bad, 1);
    if (f32bad) atomicOr(&s_f32bad, 1);
    __syncthreads();
    if (threadIdx.x == 0) {
        int mode;
        if (!s_i32bad)      mode = 0;
        else if (!s_u8bad)  mode = 1;
        else if (!s_f32bad) mode = 2;
        else                mode = 1;
        g_mask_mode = mode;
    }
}

// ---------------- reductions ---------------------------------------------------
__device__ __forceinline__ float warpReduceMax(float v) {
    #pragma unroll
    for (int o = 16; o > 0; o >>= 1) v = fmaxf(v, __shfl_xor_sync(0xffffffffu, v, o));
    return v;
}
__device__ __forceinline__ float warpReduceSum(float v) {
    #pragma unroll
    for (int o = 16; o > 0; o >>= 1) v += __shfl_xor_sync(0xffffffffu, v, o);
    return v;
}
__device__ __forceinline__ float blockReduceMax(float v) {
    __shared__ float s[32];
    int lane = threadIdx.x & 31, wid = threadIdx.x >> 5;
    v = warpReduceMax(v);
    if (lane == 0) s[wid] = v;
    __syncthreads();
    int nw = (blockDim.x + 31) >> 5;
    v = (threadIdx.x < nw) ? s[threadIdx.x] : -INFINITY;
    if (wid == 0) v = warpReduceMax(v);
    if (threadIdx.x == 0) s[0] = v;
    __syncthreads();
    float r = s[0];
    __syncthreads();
    return r;
}
__device__ __forceinline__ float blockReduceSum(float v) {
    __shared__ float s[32];
    int lane = threadIdx.x & 31, wid = threadIdx.x >> 5;
    v = warpReduceSum(v);
    if (lane == 0) s[wid] = v;
    __syncthreads();
    int nw = (blockDim.x + 31) >> 5;
    v = (threadIdx.x < nw) ? s[threadIdx.x] : 0.0f;
    if (wid == 0) v = warpReduceSum(v);
    if (threadIdx.x == 0) s[0] = v;
    __syncthreads();
    float r = s[0];
    __syncthreads();
    return r;
}

// ---------------- FP16 tensor-core GEMM: 2x2 warps, 64x64 warp tiles -----------
// C[M,N] = A[M,K] @ B[N,K]^T, both half K-major. CTA tile 128x128, BK=32.
// EPI: 0 = f32 C; 1 = half Ch only; 2 = fused attflat epilogue into f32 C (att).
// Requirements: M%128==0, N%128==0, K%32==0, K/32 >= 3.
constexpr int RSH = 40;                       // row stride in halfs (80B)
constexpr int TILEH = 128 * RSH;
constexpr int STAGEH = 2 * TILEH;
constexpr int H16_STAGES = 4;
constexpr int H16_SMEM = H16_STAGES * STAGEH * 2;   // 81920 bytes

template <int EPI>
__global__ __launch_bounds__(128, 2)
void gemm_h16(const __half* __restrict__ A, const __half* __restrict__ B,
              float* __restrict__ C, __half* __restrict__ Ch,
              int M, int N, int K, long sA, long sB, long sC,
              const float* __restrict__ b1, const float* __restrict__ w2)
{
    extern __shared__ __half sm[];
    const uint32_t smem0 = s2u(sm);

    const int bz = blockIdx.z;
    A += (size_t)bz * sA; B += (size_t)bz * sB;
    if (EPI == 0 || EPI == 2) C += (size_t)bz * sC;
    if (EPI == 1) Ch += (size_t)bz * sC;

    const int tid = threadIdx.x;
    const int lane = tid & 31, wid = tid >> 5;
    const int warp_m = wid & 1, warp_n = wid >> 1;   // 2 x 2 warps
    const int wRow = warp_m * 64, wCol = warp_n * 64;
    const int g = lane >> 2, q = lane & 3;
    const int rowBase = blockIdx.y * 128, colBase = blockIdx.x * 128;

    // ldmatrix per-lane byte offsets within a stage
    const uint32_t aLane = (uint32_t)(((wRow + (lane & 15)) * RSH + ((lane >> 4) << 3)) * 2);
    const uint32_t bLane = (uint32_t)(TILEH * 2 +
                           ((wCol + (lane & 15)) * RSH + ((lane >> 4) << 3)) * 2);

    const int nt = K / 32;

    auto issue = [&](int t) {
        __half* st = sm + (t % H16_STAGES) * STAGEH;
        const __half* Ag = A + (size_t)rowBase * K + t * 32;
        const __half* Bg = B + (size_t)colBase * K + t * 32;
        #pragma unroll
        for (int l = 0; l < 4; ++l) {
            int id = tid + l * 128;
            int r = id >> 2, c = (id & 3) << 3;
            cp16(s2u(st + r * RSH + c), Ag + (size_t)r * K + c);
            cp16(s2u(st + TILEH + r * RSH + c), Bg + (size_t)r * K + c);
        }
    };

    float acc[4][8][4];
    #pragma unroll
    for (int i = 0; i < 4; i++)
        #pragma unroll
        for (int j = 0; j < 8; j++)
            #pragma unroll
            for (int r = 0; r < 4; r++) acc[i][j][r] = 0.0f;

    issue(0); cp_commit();
    issue(1); cp_commit();
    issue(2); cp_commit();

    for (int kt = 0; kt < nt; ++kt) {
        cp_wait<2>();
        __syncthreads();
        if (kt + 3 < nt) issue(kt + 3);
        cp_commit();

        const uint32_t st = smem0 + (uint32_t)((kt % H16_STAGES) * STAGEH * 2);

        #pragma unroll
        for (int ks = 0; ks < 2; ++ks) {
            const uint32_t ko = (uint32_t)(ks * 32);   // 16 halfs = 32B
            uint32_t af[4][4];
            #pragma unroll
            for (int mt = 0; mt < 4; mt++)
                ldsm_x4(af[mt][0], af[mt][1], af[mt][2], af[mt][3],
                        st + aLane + (uint32_t)(mt * 16 * RSH * 2) + ko);
            uint32_t bf[8][2];
            #pragma unroll
            for (int np = 0; np < 4; np++) {
                uint32_t r0, r1, r2, r3;
                ldsm_x4(r0, r1, r2, r3,
                        st + bLane + (uint32_t)(np * 16 * RSH * 2) + ko);
                bf[2 * np][0] = r0; bf[2 * np + 1][0] = r1;
                bf[2 * np][1] = r2; bf[2 * np + 1][1] = r3;
            }
            #pragma unroll
            for (int mt = 0; mt < 4; mt++)
                #pragma unroll
                for (int nn = 0; nn < 8; nn++)
                    mma_f16(acc[mt][nn], af[mt], bf[nn]);
        }
    }

    if (EPI == 2) {
        float bb[8][2], ww[8][2];
        #pragma unroll
        for (int nn = 0; nn < 8; nn++) {
            int col = colBase + wCol + nn * 8 + 2 * q;
            bb[nn][0] = b1[col];     bb[nn][1] = b1[col + 1];
            ww[nn][0] = w2[col];     ww[nn][1] = w2[col + 1];
        }
        #pragma unroll
        for (int mt = 0; mt < 4; mt++) {
            float s0 = 0.0f, s1 = 0.0f;
            #pragma unroll
            for (int nn = 0; nn < 8; nn++) {
                float v;
                v = acc[mt][nn][0] + bb[nn][0]; if (v > 0.0f) s0 += v * ww[nn][0];
                v = acc[mt][nn][1] + bb[nn][1]; if (v > 0.0f) s0 += v * ww[nn][1];
                v = acc[mt][nn][2] + bb[nn][0]; if (v > 0.0f) s1 += v * ww[nn][0];
                v = acc[mt][nn][3] + bb[nn][1]; if (v > 0.0f) s1 += v * ww[nn][1];
            }
            s0 += __shfl_xor_sync(0xffffffffu, s0, 1);
            s0 += __shfl_xor_sync(0xffffffffu, s0, 2);
            s1 += __shfl_xor_sync(0xffffffffu, s1, 1);
            s1 += __shfl_xor_sync(0xffffffffu, s1, 2);
            if (q == 0) {
                int row = rowBase + wRow + mt * 16 + g;
                atomicAdd(&C[row], s0);
                atomicAdd(&C[row + 8], s1);
            }
        }
    } else if (EPI == 1) {
        #pragma unroll
        for (int mt = 0; mt < 4; mt++) {
            int row = rowBase + wRow + mt * 16 + g;
            #pragma unroll
            for (int nn = 0; nn < 8; nn++) {
                int col = colBase + wCol + nn * 8 + 2 * q;
                *(__half2*)(Ch + (size_t)row * N + col) =
                    __floats2half2_rn(acc[mt][nn][0], acc[mt][nn][1]);
                *(__half2*)(Ch + (size_t)(row + 8) * N + col) =
                    __floats2half2_rn(acc[mt][nn][2], acc[mt][nn][3]);
            }
        }
    } else {
        #pragma unroll
        for (int mt = 0; mt < 4; mt++) {
            int row = rowBase + wRow + mt * 16 + g;
            #pragma unroll
            for (int nn = 0; nn < 8; nn++) {
                int col = colBase + wCol + nn * 8 + 2 * q;
                *(float2*)(C + (size_t)row * N + col) =
                    make_float2(acc[mt][nn][0], acc[mt][nn][1]);
                *(float2*)(C + (size_t)(row + 8) * N + col) =
                    make_float2(acc[mt][nn][2], acc[mt][nn][3]);
            }
        }
    }
}

// ---------------- conversions ----------------------------------------------------
__global__ void f2h_kernel(const float* __restrict__ in, __half* __restrict__ out,
                           int n2)
{
    int i = blockIdx.x * blockDim.x + threadIdx.x;
    if (i < n2) {
        float2 v = ((const float2*)in)[i];
        ((__half2*)out)[i] = __floats2half2_rn(v.x, v.y);
    }
}

__global__ void transpose_f2h_kernel(const float* __restrict__ in,
                                     __half* __restrict__ out, int R, int C)
{
    __shared__ float t[32][33];
    const size_t zo = (size_t)blockIdx.z * R * C;
    const int c0 = blockIdx.x * 32, r0 = blockIdx.y * 32;
    #pragma unroll
    for (int i = threadIdx.y; i < 32; i += 8)
        t[i][threadIdx.x] = in[zo + (size_t)(r0 + i) * C + c0 + threadIdx.x];
    __syncthreads();
    #pragma unroll
    for (int i = threadIdx.y; i < 32; i += 8)
        out[zo + (size_t)(c0 + i) * R + r0 + threadIdx.x] =
            __float2half_rn(t[threadIdx.x][i]);
}

// ---------------- softmaxes -------------------------------------------------------
__global__ void attn_softmax_h(const float* __restrict__ scores,
                               __half* __restrict__ outh,
                               const void* __restrict__ mask,
                               int rowsPerBatch, int Nk, float scale)
{
    const int row = blockIdx.x;
    const int b = row / rowsPerBatch;
    const int mode = g_mask_mode;
    const float* s = scores + (size_t)row * Nk;
    __half* o = outh + (size_t)row * Nk;
    const int vpt = Nk >> 7;

    float v[4];
    float lmax = -INFINITY;
    for (int j = 0; j < vpt; ++j) {
        int k = threadIdx.x + (j << 7);
        float x = mask_at(mask, (size_t)b * Nk + k, mode) ? NEGV : s[k] * scale;
        v[j] = x;
        lmax = fmaxf(lmax, x);
    }
    float rmax = blockReduceMax(lmax);
    float lsum = 0.0f;
    for (int j = 0; j < vpt; ++j) {
        v[j] = __expf(v[j] - rmax);
        lsum += v[j];
    }
    float inv = 1.0f / blockReduceSum(lsum);
    for (int j = 0; j < vpt; ++j) {
        int k = threadIdx.x + (j << 7);
        o[k] = __float2half_rn(v[j] * inv);
    }
}

__global__ void flat_softmax_kernel(float* __restrict__ att,
                                    const void* __restrict__ mask,
                                    int Nt, float* __restrict__ weightOut)
{
    const int b = blockIdx.x;
    const int mode = g_mask_mode;
    float* a = att + (size_t)b * Nt;

    float lmax = -INFINITY;
    for (int t = threadIdx.x; t < Nt; t += blockDim.x) {
        float v = mask_at(mask, (size_t)b * Nt + t, mode) ? NEGV : a[t];
        a[t] = v;
        lmax = fmaxf(lmax, v);
    }
    float rmax = blockReduceMax(lmax);
    float lsum = 0.0f;
    for (int t = threadIdx.x; t < Nt; t += blockDim.x) {
        float e = __expf(a[t] - rmax);
        a[t] = e;
        lsum += e;
    }
    float inv = 1.0f / blockReduceSum(lsum);
    for (int t = threadIdx.x; t < Nt; t += blockDim.x) {
        float p = a[t] * inv;
        a[t] = p;
        if (weightOut) weightOut[(size_t)b * Nt + t] = p;
    }
}

// ---------------- pooled = sum_t att[b,t]*x[b,t,:]  (x in half) -------------------
__global__ void pool_kernel(const __half* __restrict__ x, const float* __restrict__ att,
                            float* __restrict__ pooled, int Nt)
{
    const int b = blockIdx.x;
    const int d = blockIdx.y * 128 + threadIdx.x;
    __shared__ float a[512];
    for (int t = threadIdx.x; t < Nt; t += blockDim.x) a[t] = att[(size_t)b * Nt + t];
    __syncthreads();
    const __half* xb = x + (size_t)b * Nt * 640;
    float s = 0.0f;
    for (int t = 0; t < Nt; t++) s += a[t] * __half2float(xb[(size_t)t * 640 + d]);
    pooled[(size_t)b * 640 + d] = s;
}

// ---------------- out = pooled @ Wm + bm  (64x640x640) ----------------------------
__global__ void final_linear_kernel(const float* __restrict__ pooled,
                                    const float* __restrict__ Wm,
                                    const float* __restrict__ bm,
                                    float* __restrict__ out)
{
    const int b = blockIdx.x;
    const int n = blockIdx.y * 128 + threadIdx.x;
    __shared__ float p[640];
    for (int i = threadIdx.x; i < 640; i += blockDim.x) p[i] = pooled[(size_t)b * 640 + i];
    __syncthreads();
    float s = bm[n];
    for (int k = 0; k < 640; k++) s += p[k] * Wm[(size_t)k * 640 + n];
    out[(size_t)b * 640 + n] = s;
}

__global__ void zero_kernel(float* __restrict__ p, int n) {
    int i = blockIdx.x * blockDim.x + threadIdx.x;
    if (i < n) p[i] = 0.0f;
}

// ---------------- launch ------------------------------------------------------------
extern "C" void kernel_launch(void* const* d_in, const int* in_sizes, int n_in,
                              void* d_out, int out_size)
{
    const float* i_batch = (const float*)d_in[0];   // [64,512,640]
    const float* q_batch = (const float*)d_in[1];   // [64,128,640]
    const void*  i_mask  = d_in[2];                 // [64,512]
    const void*  q_mask  = d_in[3];                 // [64,128]
    const float* lW1 = (const float*)d_in[4];
    const float* lb1 = (const float*)d_in[5];
    const float* lW2 = (const float*)d_in[6];
    const float* lWm = (const float*)d_in[8];
    const float* lbm = (const float*)d_in[9];
    const float* iW1 = (const float*)d_in[10];
    const float* ib1 = (const float*)d_in[11];
    const float* iW2 = (const float*)d_in[12];
    const float* iWm = (const float*)d_in[14];
    const float* ibm = (const float*)d_in[15];
    float* out = (float*)d_out;                     // i_feat | l_feat | i_weight

    float *scores, *att, *pooled;
    __half *scores_h, *x_h, *i_h, *q_h, *vT1, *iT, *w1t, *iw1t;
    cudaGetSymbolAddress((void**)&scores, g_scores);
    cudaGetSymbolAddress((void**)&scores_h, g_scores_h);
    cudaGetSymbolAddress((void**)&x_h, g_x_h);
    cudaGetSymbolAddress((void**)&i_h, g_i_h);
    cudaGetSymbolAddress((void**)&q_h, g_q_h);
    cudaGetSymbolAddress((void**)&vT1, g_vT1);
    cudaGetSymbolAddress((void**)&iT, g_iT);
    cudaGetSymbolAddress((void**)&w1t, g_w1t);
    cudaGetSymbolAddress((void**)&iw1t, g_iw1t);
    cudaGetSymbolAddress((void**)&att, g_att);
    cudaGetSymbolAddress((void**)&pooled, g_pooled);

    const float scale = 1.0f / sqrtf(640.0f);
    const int B = 64, Ni = 512, Nq = 128, D = 640, H = 1280;

    cudaFuncSetAttribute(gemm_h16<0>, cudaFuncAttributeMaxDynamicSharedMemorySize, H16_SMEM);
    cudaFuncSetAttribute(gemm_h16<1>, cudaFuncAttributeMaxDynamicSharedMemorySize, H16_SMEM);
    cudaFuncSetAttribute(gemm_h16<2>, cudaFuncAttributeMaxDynamicSharedMemorySize, H16_SMEM);

    detect_mask_kernel<<<1, 256>>>((const unsigned int*)i_mask, 8192);

    // ---- prep: conversions + transposes ----
    f2h_kernel<<<(B * Ni * D / 2 + 255) / 256, 256>>>(i_batch, i_h, B * Ni * D / 2);
    f2h_kernel<<<(B * Nq * D / 2 + 255) / 256, 256>>>(q_batch, q_h, B * Nq * D / 2);
    transpose_f2h_kernel<<<dim3(D / 32, Nq / 32, B), dim3(32, 8)>>>(q_batch, vT1, Nq, D);
    transpose_f2h_kernel<<<dim3(D / 32, Ni / 32, B), dim3(32, 8)>>>(i_batch, iT, Ni, D);
    transpose_f2h_kernel<<<dim3(H / 32, D / 32, 1), dim3(32, 8)>>>(lW1, w1t, D, H);
    transpose_f2h_kernel<<<dim3(H / 32, D / 32, 1), dim3(32, 8)>>>(iW1, iw1t, D, H);

    // ===== Phase 1: attn(q=i_batch, k/v=q_batch, mask=q_mask) =====
    gemm_h16<0><<<dim3(1, 4, B), 128, H16_SMEM>>>(
        i_h, q_h, scores, nullptr, Ni, Nq, D,
        (long)Ni * D, (long)Nq * D, (long)Ni * Nq, nullptr, nullptr);
    attn_softmax_h<<<B * Ni, 128>>>(scores, scores_h, q_mask, Ni, Nq, scale);
    gemm_h16<1><<<dim3(5, 4, B), 128, H16_SMEM>>>(
        scores_h, vT1, nullptr, x_h, Ni, D, Nq,
        (long)Ni * Nq, (long)D * Nq, (long)Ni * D, nullptr, nullptr);

    // ===== Phase 2: attflat(x1, i_mask, lW*) =====
    zero_kernel<<<(B * Ni + 255) / 256, 256>>>(att, B * Ni);
    gemm_h16<2><<<dim3(H / 128, (B * Ni) / 128, 1), 128, H16_SMEM>>>(
        x_h, w1t, att, nullptr, B * Ni, H, D, 0, 0, 0, lb1, lW2);
    flat_softmax_kernel<<<B, 256>>>(att, i_mask, Ni, out + 2 * B * D);   // i_weight
    pool_kernel<<<dim3(B, 5), 128>>>(x_h, att, pooled, Ni);
    final_linear_kernel<<<dim3(B, 5), 128>>>(pooled, lWm, lbm, out);     // i_feat

    // ===== Phase 3: attn(q=q_batch, k/v=i_batch, mask=i_mask) =====
    gemm_h16<0><<<dim3(4, 1, B), 128, H16_SMEM>>>(
        q_h, i_h, scores, nullptr, Nq, Ni, D,
        (long)Nq * D, (long)Ni * D, (long)Nq * Ni, nullptr, nullptr);
    attn_softmax_h<<<B * Nq, 128>>>(scores, scores_h, i_mask, Nq, Ni, scale);
    gemm_h16<1><<<dim3(5, 1, B), 128, H16_SMEM>>>(
        scores_h, iT, nullptr, x_h, Nq, D, Ni,
        (long)Nq * Ni, (long)D * Ni, (long)Nq * D, nullptr, nullptr);

    // ===== Phase 4: attflat(x2, q_mask, iW*) =====
    zero_kernel<<<(B * Nq + 255) / 256, 256>>>(att, B * Nq);
    gemm_h16<2><<<dim3(H / 128, (B * Nq) / 128, 1), 128, H16_SMEM>>>(
        x_h, iw1t, att, nullptr, B * Nq, H, D, 0, 0, 0, ib1, iW2);
    flat_softmax_kernel<<<B, 128>>>(att, q_mask, Nq, nullptr);
    pool_kernel<<<dim3(B, 5), 128>>>(x_h, att, pooled, Nq);
    final_linear_kernel<<<dim3(B, 5), 128>>>(pooled, iWm, ibm, out + B * D);  // l_feat
}